// round 9
// baseline (speedup 1.0000x reference)
#include <cuda_runtime.h>
#include <cuda_bf16.h>
#include <math.h>
#include <stdint.h>

// Problem dims
#define BB   4
#define LL   1024
#define DD   512
#define CHI  32
#define SS   4
#define NT   (BB*LL)          // 4096 tokens
#define CSC  (CHI*SS*CHI)     // 4096

// ---------------- scratch (__device__ globals, no allocs) ----------------
__device__ float g_site[(size_t)NT * CSC];       // x @ W_site + b_site     (64 MB)
__device__ float g_gate[(size_t)NT * DD];        // x @ W_gate + b_gate
__device__ float g_Bmat[(size_t)NT * CHI * CHI]; // B_t stored [t][r*32+l]
__device__ float g_WB[512 * 1024];               // pre-reduced site weights (fp32)
__device__ float g_bB[1024];                     // pre-reduced site bias
__device__ float g_c[(size_t)NT * CHI];          // c_t[r] = u_t @ B_t
__device__ float g_left[(size_t)NT * CHI];       // recorded left vectors
__device__ float g_y[(size_t)NT * DD];           // pre-LN y
__device__ float g_Wco[128 * 512];               // W_bridge @ W_out (fp32)
__device__ float g_bco[512];                     // b_bridge @ W_out + b_out

// pre-converted bf16 split operands
__device__ __nv_bfloat16 g_xh[(size_t)NT * DD],   g_xl[(size_t)NT * DD];
__device__ __nv_bfloat16 g_WsT_h[(size_t)CSC * DD], g_WsT_l[(size_t)CSC * DD];   // [n][k]
__device__ __nv_bfloat16 g_WgT_h[DD * DD],        g_WgT_l[DD * DD];
__device__ __nv_bfloat16 g_WBT_h[1024 * DD],      g_WBT_l[1024 * DD];
__device__ __nv_bfloat16 g_WcoT_h[DD * 128],      g_WcoT_l[DD * 128];
__device__ __nv_bfloat16 g_mh[(size_t)NT * 128],  g_ml[(size_t)NT * 128];

// ---------------- helpers ----------------
__device__ __forceinline__ uint32_t smem_u32(const void* p) {
    uint32_t a;
    asm("{ .reg .u64 t; cvta.to.shared.u64 t, %1; cvt.u32.u64 %0, t; }" : "=r"(a) : "l"(p));
    return a;
}
__device__ __forceinline__ void bsplit(float v, __nv_bfloat16& h, __nv_bfloat16& l)
{
    h = __float2bfloat16(v);
    l = __float2bfloat16(v - __bfloat162float(h));
}
#define CPA16(dst, src)  asm volatile("cp.async.cg.shared.global [%0], [%1], 16;" :: "r"(dst), "l"(src))
#define CPA_COMMIT()     asm volatile("cp.async.commit_group;" ::: "memory")
#define CPA_WAIT0()      asm volatile("cp.async.wait_group 0;" ::: "memory")
#define CPA_WAIT1()      asm volatile("cp.async.wait_group 1;" ::: "memory")

#define MMA_BF16(d, a0, a1, a2, a3, b0, b1)                                   \
    asm volatile("mma.sync.aligned.m16n8k16.row.col.f32.bf16.bf16.f32 "       \
                 "{%0,%1,%2,%3}, {%4,%5,%6,%7}, {%8,%9}, {%0,%1,%2,%3};\n"    \
                 : "+f"(d[0]), "+f"(d[1]), "+f"(d[2]), "+f"(d[3])             \
                 : "r"(a0), "r"(a1), "r"(a2), "r"(a3), "r"(b0), "r"(b1))

#define LDSM4(r, addr)                                                        \
    asm volatile("ldmatrix.sync.aligned.m8n8.x4.shared.b16 {%0,%1,%2,%3}, [%4];" \
                 : "=r"((r)[0]), "=r"((r)[1]), "=r"((r)[2]), "=r"((r)[3])     \
                 : "r"(addr))

// ---------------- x -> bf16 split ----------------
__global__ void xcvt_kernel(const float* __restrict__ x)
{
    int i = blockIdx.x * 256 + threadIdx.x;      // NT*DD = 2M
    __nv_bfloat16 h, l;
    bsplit(x[i], h, l);
    g_xh[i] = h; g_xl[i] = l;
}

// ---------------- transpose + split: src[K][N] fp32 -> dh/dl[N][K] bf16 ----
__global__ void tsplit_kernel(const float* __restrict__ src,
                              __nv_bfloat16* __restrict__ dh,
                              __nv_bfloat16* __restrict__ dl, int K, int N)
{
    __shared__ float t[32][33];
    int bn = blockIdx.x * 32, bk = blockIdx.y * 32;
    int tx = threadIdx.x, ty = threadIdx.y;
#pragma unroll
    for (int i = ty; i < 32; i += 8)
        t[i][tx] = src[(size_t)(bk + i) * N + bn + tx];
    __syncthreads();
#pragma unroll
    for (int i = ty; i < 32; i += 8) {
        __nv_bfloat16 h, l;
        bsplit(t[tx][i], h, l);                  // = src[bk+tx][bn+i]
        dh[(size_t)(bn + i) * K + bk + tx] = h;
        dl[(size_t)(bn + i) * K + bk + tx] = l;
    }
}

// ---------------- prep: fuse bridge+out weights (fp32) ----------------
__global__ void prep_kernel(const float* __restrict__ Wb, const float* __restrict__ bb,
                            const float* __restrict__ Wo, const float* __restrict__ bo)
{
    int idx = blockIdx.x * blockDim.x + threadIdx.x;   // 0..65535
    int pr = idx >> 9, j = idx & 511;
    float s = 0.f;
#pragma unroll
    for (int i = 0; i < 32; ++i)
        s = fmaf(Wb[pr * 32 + i], Wo[i * 512 + j], s);
    g_Wco[idx] = s;
    if (idx < 512) {
        float c = bo[idx];
#pragma unroll
        for (int i = 0; i < 32; ++i)
            c = fmaf(bb[i], Wo[i * 512 + idx], c);
        g_bco[idx] = c;
    }
}

// ---------------- reduce W_site over physical index -> W_B (fp32) ----------
__global__ __launch_bounds__(256) void wb_kernel(const float* __restrict__ Ws,
                                                 const float* __restrict__ bs)
{
    int idx = blockIdx.x * 256 + threadIdx.x;          // 0 .. 512*1024-1
    int d = idx >> 10, rem = idx & 1023;
    int l = rem >> 5, r = rem & 31;
    const float* p = Ws + (size_t)d * 4096 + l * 128 + r;   // coalesced in r
    g_WB[(size_t)d * 1024 + r * 32 + l] = p[0] + p[32] + p[64] + p[96];
    if (idx < 1024) {
        int ll = idx >> 5, rr = idx & 31;
        const float* q = bs + ll * 128 + rr;
        g_bB[rr * 32 + ll] = q[0] + q[32] + q[64] + q[96];
    }
}

// ============ bf16-split tensor GEMM: C = A[MxK] @ B[KxN] + bias ===========
// A split (Ah,Al) row-major [M][K]; B split TRANSPOSED [N][K]. 3-term MMA.
// Tile 128x128, BK=32, double-buffered cp.async, ldmatrix fragment loads.
#define HG_SMEM (2 * 40960)

__device__ __forceinline__ void hg_load(uint32_t sb,
    const __nv_bfloat16* __restrict__ Ah, const __nv_bfloat16* __restrict__ Al,
    const __nv_bfloat16* __restrict__ Bh, const __nv_bfloat16* __restrict__ Bl,
    int bm, int bn, int K, int k0, int tid)
{
#pragma unroll
    for (int q = 0; q < 2; ++q) {
        int id = tid + 256 * q;                  // 0..511
        int r = id >> 2, c = id & 3;
        uint32_t so = (uint32_t)(r * 80 + c * 16);
        size_t goA = (size_t)(bm + r) * K + k0 + c * 8;
        size_t goB = (size_t)(bn + r) * K + k0 + c * 8;
        CPA16(sb + so,          Ah + goA);
        CPA16(sb + 10240 + so,  Al + goA);
        CPA16(sb + 20480 + so,  Bh + goB);
        CPA16(sb + 30720 + so,  Bl + goB);
    }
}

// ldmatrix-based fragment loads. Lane-address maps (verified against the
// mma.m16n8k16 fragment layout):
//  A x4: lane l -> row m0 + (l&15), byte-col (l>>4)*16   => regs {a0,a1,a2,a3}
//  B x4 (two n8 blocks): lane l -> row n0 + (l&7) + ((l>>4)<<3),
//        byte-col ((l>>3)&1)*16  => regs {b0(n0),b1(n0),b0(n0+8),b1(n0+8)}
__device__ __forceinline__ void hg_compute(uint32_t sb, float acc[4][4][4],
                                           int m0w, int n0w, int lane)
{
    const int arow = (lane & 15);
    const int acolb = (lane >> 4) * 16;
    const int brow = (lane & 7) + ((lane >> 4) << 3);
    const int bcolb = ((lane >> 3) & 1) * 16;
#pragma unroll
    for (int kk = 0; kk < 2; ++kk) {
        const int kb = kk * 32;                  // 16 bf16 = 32 bytes
        uint32_t ah[4][4], al[4][4], bh[2][4], bl[2][4];
#pragma unroll
        for (int mi = 0; mi < 4; ++mi) {
            uint32_t adr = sb + (uint32_t)((m0w + mi * 16 + arow) * 80 + kb + acolb);
            LDSM4(ah[mi], adr);
            LDSM4(al[mi], adr + 10240);
        }
#pragma unroll
        for (int np = 0; np < 2; ++np) {
            uint32_t adr = sb + 20480 + (uint32_t)((n0w + np * 16 + brow) * 80 + kb + bcolb);
            LDSM4(bh[np], adr);
            LDSM4(bl[np], adr + 10240);
        }
#pragma unroll
        for (int ni = 0; ni < 4; ++ni) {
            uint32_t h0 = bh[ni >> 1][(ni & 1) * 2], h1 = bh[ni >> 1][(ni & 1) * 2 + 1];
            uint32_t l0 = bl[ni >> 1][(ni & 1) * 2], l1 = bl[ni >> 1][(ni & 1) * 2 + 1];
#pragma unroll
            for (int mi = 0; mi < 4; ++mi) {
                MMA_BF16(acc[mi][ni], ah[mi][0], ah[mi][1], ah[mi][2], ah[mi][3], h0, h1);
                MMA_BF16(acc[mi][ni], ah[mi][0], ah[mi][1], ah[mi][2], ah[mi][3], l0, l1);
                MMA_BF16(acc[mi][ni], al[mi][0], al[mi][1], al[mi][2], al[mi][3], h0, h1);
            }
        }
    }
}

__global__ __launch_bounds__(256, 1)
void hgemm2_kernel(const __nv_bfloat16* __restrict__ Ah, const __nv_bfloat16* __restrict__ Al,
                   const __nv_bfloat16* __restrict__ Bh, const __nv_bfloat16* __restrict__ Bl,
                   const float* __restrict__ bias, float* __restrict__ C,
                   int M, int N, int K)
{
    extern __shared__ __align__(16) char smem[];
    const int tid = threadIdx.x;
    const int warp = tid >> 5, lane = tid & 31;
    const int g = lane >> 2, tg = lane & 3;
    const int m0w = (warp >> 2) * 64;            // 0 | 64
    const int n0w = (warp & 3) * 32;             // 0..96
    const int bm = blockIdx.y * 128, bn = blockIdx.x * 128;
    const uint32_t sb = smem_u32(smem);

    float acc[4][4][4];
#pragma unroll
    for (int i = 0; i < 4; ++i)
#pragma unroll
        for (int j = 0; j < 4; ++j)
#pragma unroll
            for (int e = 0; e < 4; ++e) acc[i][j][e] = 0.f;

    const int nk = K >> 5;
    hg_load(sb, Ah, Al, Bh, Bl, bm, bn, K, 0, tid);
    CPA_COMMIT();
    for (int i = 0; i < nk; ++i) {
        if (i + 1 < nk) {
            hg_load(sb + ((i + 1) & 1) * 40960, Ah, Al, Bh, Bl, bm, bn, K, (i + 1) * 32, tid);
            CPA_COMMIT();
            CPA_WAIT1();
        } else {
            CPA_WAIT0();
        }
        __syncthreads();
        hg_compute(sb + (uint32_t)((i & 1) * 40960), acc, m0w, n0w, lane);
        __syncthreads();
    }

#pragma unroll
    for (int mi = 0; mi < 4; ++mi) {
        int row = bm + m0w + mi * 16 + g;
#pragma unroll
        for (int ni = 0; ni < 4; ++ni) {
            int col = bn + n0w + ni * 8 + 2 * tg;
            float b0 = bias[col], b1 = bias[col + 1];
            *(float2*)&C[(size_t)row * N + col] =
                make_float2(acc[mi][ni][0] + b0, acc[mi][ni][1] + b1);
            *(float2*)&C[(size_t)(row + 8) * N + col] =
                make_float2(acc[mi][ni][2] + b0, acc[mi][ni][3] + b1);
        }
    }
}

// ---------------- c_t[r] = sum_l u_t[l] * B_t[l][r] (8 tokens/block) -------
__global__ __launch_bounds__(256) void c_kernel(const float* __restrict__ x)
{
    int t = blockIdx.x * 8 + (threadIdx.x >> 5);
    int r = threadIdx.x & 31;
    float u = x[(size_t)t * DD + r];           // lane l holds u_l
    const float* brow = g_Bmat + (size_t)t * 1024 + r * 32;
    float4 b4[8];
#pragma unroll
    for (int q = 0; q < 8; ++q) b4[q] = __ldg((const float4*)(brow + 4 * q));
    float c = 0.f;
#pragma unroll
    for (int q = 0; q < 8; ++q) {
        c = fmaf(__shfl_sync(0xffffffffu, u, 4 * q + 0), b4[q].x, c);
        c = fmaf(__shfl_sync(0xffffffffu, u, 4 * q + 1), b4[q].y, c);
        c = fmaf(__shfl_sync(0xffffffffu, u, 4 * q + 2), b4[q].z, c);
        c = fmaf(__shfl_sync(0xffffffffu, u, 4 * q + 3), b4[q].w, c);
    }
    g_c[(size_t)t * 32 + r] = c;
}

// ---------------- sequential scan: one warp per batch, prefetch depth 2 ----
// (R6 formulation: norm accumulated from the same shfl broadcasts, no butterfly)
__device__ __forceinline__ float scan_step(float v, const float4* BC, float cc,
                                           float uu, float* leftp)
{
    float w0 = 0.f, w1 = 0.f, w2 = 0.f, w3 = 0.f;
    float s0 = 0.f, s1 = 0.f, s2 = 0.f, s3 = 0.f;
#pragma unroll
    for (int q = 0; q < 8; q += 4) {
        float va, vb, vc, vd;
        va = __shfl_sync(0xffffffffu, v, 4*q + 0);
        vb = __shfl_sync(0xffffffffu, v, 4*q + 1);
        vc = __shfl_sync(0xffffffffu, v, 4*q + 2);
        vd = __shfl_sync(0xffffffffu, v, 4*q + 3);
        w0 = fmaf(va, BC[q].x, w0); s0 = fmaf(va, va, s0);
        w0 = fmaf(vb, BC[q].y, w0); s0 = fmaf(vb, vb, s0);
        w0 = fmaf(vc, BC[q].z, w0); s0 = fmaf(vc, vc, s0);
        w0 = fmaf(vd, BC[q].w, w0); s0 = fmaf(vd, vd, s0);
        va = __shfl_sync(0xffffffffu, v, 4*q + 4);
        vb = __shfl_sync(0xffffffffu, v, 4*q + 5);
        vc = __shfl_sync(0xffffffffu, v, 4*q + 6);
        vd = __shfl_sync(0xffffffffu, v, 4*q + 7);
        w1 = fmaf(va, BC[q+1].x, w1); s1 = fmaf(va, va, s1);
        w1 = fmaf(vb, BC[q+1].y, w1); s1 = fmaf(vb, vb, s1);
        w1 = fmaf(vc, BC[q+1].z, w1); s1 = fmaf(vc, vc, s1);
        w1 = fmaf(vd, BC[q+1].w, w1); s1 = fmaf(vd, vd, s1);
        va = __shfl_sync(0xffffffffu, v, 4*q + 8);
        vb = __shfl_sync(0xffffffffu, v, 4*q + 9);
        vc = __shfl_sync(0xffffffffu, v, 4*q + 10);
        vd = __shfl_sync(0xffffffffu, v, 4*q + 11);
        w2 = fmaf(va, BC[q+2].x, w2); s2 = fmaf(va, va, s2);
        w2 = fmaf(vb, BC[q+2].y, w2); s2 = fmaf(vb, vb, s2);
        w2 = fmaf(vc, BC[q+2].z, w2); s2 = fmaf(vc, vc, s2);
        w2 = fmaf(vd, BC[q+2].w, w2); s2 = fmaf(vd, vd, s2);
        va = __shfl_sync(0xffffffffu, v, 4*q + 12);
        vb = __shfl_sync(0xffffffffu, v, 4*q + 13);
        vc = __shfl_sync(0xffffffffu, v, 4*q + 14);
        vd = __shfl_sync(0xffffffffu, v, 4*q + 15);
        w3 = fmaf(va, BC[q+3].x, w3); s3 = fmaf(va, va, s3);
        w3 = fmaf(vb, BC[q+3].y, w3); s3 = fmaf(vb, vb, s3);
        w3 = fmaf(vc, BC[q+3].z, w3); s3 = fmaf(vc, vc, s3);
        w3 = fmaf(vd, BC[q+3].w, w3); s3 = fmaf(vd, vd, s3);
    }
    float w = (w0 + w1) + (w2 + w3);
    float s = (s0 + s1) + (s2 + s3);
    float alpha = rsqrtf(s + 1e-24f);          // s==0 -> alpha*v == 0 == h0
    *leftp = fmaf(alpha, v, uu);
    return fmaf(alpha, w, cc);
}

__global__ void scan_kernel(const float* __restrict__ x)
{
    const int b = blockIdx.x;
    const int r = threadIdx.x;                 // 0..31
    const size_t tg0 = (size_t)b * LL;
    const float* Bbase = g_Bmat + tg0 * 1024 + r * 32;
    const float* cbase = g_c + tg0 * 32 + r;
    const float* ubase = x + tg0 * DD + r;
    float* lp = g_left + tg0 * 32 + r;

    float4 b0[8], b1[8], b2[8];
    float c0, c1, c2, u0, u1, u2;

#define PREF(PT, BUF, CC, UU) { \
        int tp_ = (PT); if (tp_ > (LL-1)) tp_ = LL-1; \
        const float* bp_ = Bbase + (size_t)tp_ * 1024; \
        BUF[0] = __ldg((const float4*)(bp_ + 0));  BUF[1] = __ldg((const float4*)(bp_ + 4)); \
        BUF[2] = __ldg((const float4*)(bp_ + 8));  BUF[3] = __ldg((const float4*)(bp_ + 12)); \
        BUF[4] = __ldg((const float4*)(bp_ + 16)); BUF[5] = __ldg((const float4*)(bp_ + 20)); \
        BUF[6] = __ldg((const float4*)(bp_ + 24)); BUF[7] = __ldg((const float4*)(bp_ + 28)); \
        CC = __ldg(cbase + (size_t)tp_ * 32); \
        UU = __ldg(ubase + (size_t)tp_ * DD); }

    PREF(0, b0, c0, u0);
    PREF(1, b1, c1, u1);
    float v = 0.f;

#pragma unroll 1
    for (int t = 0; t < LL - 1; t += 3) {
        PREF(t + 2, b2, c2, u2);
        v = scan_step(v, b0, c0, u0, lp); lp += 32;
        PREF(t + 3, b0, c0, u0);
        v = scan_step(v, b1, c1, u1, lp); lp += 32;
        PREF(t + 4, b1, c1, u1);
        v = scan_step(v, b2, c2, u2, lp); lp += 32;
    }
    // main loop covers t = 0..1022 (341 blocks of 3); tail t = 1023 in b0
    v = scan_step(v, b0, c0, u0, lp);
#undef PREF
}

// ------- recover Mt per token; emit bf16 split for the final GEMM ----------
__global__ __launch_bounds__(128) void mrec_kernel()
{
    __shared__ float sleft[32];
    int t = blockIdx.x, tid = threadIdx.x;
    if (tid < 32) sleft[tid] = g_left[(size_t)t * 32 + tid];
    __syncthreads();
    const float* row = g_site + (size_t)t * CSC;
    float m = 0.f;
#pragma unroll
    for (int l = 0; l < 32; ++l)
        m = fmaf(sleft[l], __ldcs(row + l * 128 + tid), m);   // streaming, coalesced
    __nv_bfloat16 h, lo;
    bsplit(m, h, lo);
    g_mh[(size_t)t * 128 + tid] = h;
    g_ml[(size_t)t * 128 + tid] = lo;
}

// ---------------- LayerNorm + sigmoid-gated residual ----------------
__global__ __launch_bounds__(256) void post_kernel(const float* __restrict__ x,
                                                   const float* __restrict__ gamma,
                                                   const float* __restrict__ beta,
                                                   float* __restrict__ out)
{
    __shared__ float red[256];
    int t = blockIdx.x, tid = threadIdx.x;
    size_t base = (size_t)t * DD;
    int j0 = tid, j1 = tid + 256;
    float y0 = g_y[base + j0], y1 = g_y[base + j1];

    red[tid] = y0 + y1;
    __syncthreads();
    for (int st = 128; st > 0; st >>= 1) {
        if (tid < st) red[tid] += red[tid + st];
        __syncthreads();
    }
    float mu = red[0] * (1.f / 512.f);
    __syncthreads();

    float d0 = y0 - mu, d1 = y1 - mu;
    red[tid] = d0 * d0 + d1 * d1;
    __syncthreads();
    for (int st = 128; st > 0; st >>= 1) {
        if (tid < st) red[tid] += red[tid + st];
        __syncthreads();
    }
    float var = red[0] * (1.f / 512.f);
    float rstd = rsqrtf(var + 1e-6f);

    float yn0 = d0 * rstd * gamma[j0] + beta[j0];
    float yn1 = d1 * rstd * gamma[j1] + beta[j1];
    float gl0 = g_gate[base + j0], gl1 = g_gate[base + j1];
    float gt0 = 1.f / (1.f + expf(-gl0));
    float gt1 = 1.f / (1.f + expf(-gl1));
    float xv0 = x[base + j0], xv1 = x[base + j1];
    out[base + j0] = gt0 * yn0 + (1.f - gt0) * xv0;
    out[base + j1] = gt1 * yn1 + (1.f - gt1) * xv1;
}

// ---------------- launch ----------------
extern "C" void kernel_launch(void* const* d_in, const int* in_sizes, int n_in,
                              void* d_out, int out_size)
{
    (void)in_sizes; (void)n_in; (void)out_size;
    const float* x       = (const float*)d_in[0];
    const float* W_site  = (const float*)d_in[1];
    const float* b_site  = (const float*)d_in[2];
    const float* W_bridge= (const float*)d_in[3];
    const float* b_bridge= (const float*)d_in[4];
    const float* W_out   = (const float*)d_in[5];
    const float* b_out   = (const float*)d_in[6];
    const float* gamma   = (const float*)d_in[7];
    const float* beta    = (const float*)d_in[8];
    const float* W_gate  = (const float*)d_in[9];
    const float* b_gate  = (const float*)d_in[10];
    float* out = (float*)d_out;

    static float *p_site, *p_gate, *p_y, *p_WB, *p_bB, *p_Wco, *p_bco, *p_Bmat;
    static __nv_bfloat16 *p_xh, *p_xl, *p_WsTh, *p_WsTl, *p_WgTh, *p_WgTl,
                         *p_WBTh, *p_WBTl, *p_WcoTh, *p_WcoTl, *p_mh, *p_ml;
    static cudaStream_t s1;
    static cudaEvent_t ev0, evS, evG;
    static bool inited = false;
    if (!inited) {
        cudaGetSymbolAddress((void**)&p_site,  g_site);
        cudaGetSymbolAddress((void**)&p_gate,  g_gate);
        cudaGetSymbolAddress((void**)&p_y,     g_y);
        cudaGetSymbolAddress((void**)&p_WB,    g_WB);
        cudaGetSymbolAddress((void**)&p_bB,    g_bB);
        cudaGetSymbolAddress((void**)&p_Wco,   g_Wco);
        cudaGetSymbolAddress((void**)&p_bco,   g_bco);
        cudaGetSymbolAddress((void**)&p_Bmat,  g_Bmat);
        cudaGetSymbolAddress((void**)&p_xh,    g_xh);
        cudaGetSymbolAddress((void**)&p_xl,    g_xl);
        cudaGetSymbolAddress((void**)&p_WsTh,  g_WsT_h);
        cudaGetSymbolAddress((void**)&p_WsTl,  g_WsT_l);
        cudaGetSymbolAddress((void**)&p_WgTh,  g_WgT_h);
        cudaGetSymbolAddress((void**)&p_WgTl,  g_WgT_l);
        cudaGetSymbolAddress((void**)&p_WBTh,  g_WBT_h);
        cudaGetSymbolAddress((void**)&p_WBTl,  g_WBT_l);
        cudaGetSymbolAddress((void**)&p_WcoTh, g_WcoT_h);
        cudaGetSymbolAddress((void**)&p_WcoTl, g_WcoT_l);
        cudaGetSymbolAddress((void**)&p_mh,    g_mh);
        cudaGetSymbolAddress((void**)&p_ml,    g_ml);
        cudaStreamCreateWithFlags(&s1, cudaStreamNonBlocking);
        cudaEventCreateWithFlags(&ev0, cudaEventDisableTiming);
        cudaEventCreateWithFlags(&evS, cudaEventDisableTiming);
        cudaEventCreateWithFlags(&evG, cudaEventDisableTiming);
        cudaFuncSetAttribute(hgemm2_kernel, cudaFuncAttributeMaxDynamicSharedMemorySize, HG_SMEM);
        inited = true;
    }

    // shared prologue: x split (both branches need it)
    xcvt_kernel<<<(NT * DD) / 256, 256>>>(x);                        // #1
    cudaEventRecord(ev0, 0);
    cudaStreamWaitEvent(s1, ev0, 0);

    // ---- side stream: site GEMM FIRST (lands in ncu's profiled slot) ----
    tsplit_kernel<<<dim3(128,16), dim3(32, 8), 0, s1>>>(W_site, p_WsTh, p_WsTl, 512, 4096); // #2
    prep_kernel<<<256, 256, 0, s1>>>(W_bridge, b_bridge, W_out, b_out);                     // #3
    hgemm2_kernel<<<dim3(CSC/128, NT/128), 256, HG_SMEM, s1>>>(
        p_xh, p_xl, p_WsTh, p_WsTl, b_site, p_site, NT, CSC, DD);                           // #4 (profiled)
    cudaEventRecord(evS, s1);
    tsplit_kernel<<<dim3(16, 4),  dim3(32, 8), 0, s1>>>(p_Wco,  p_WcoTh, p_WcoTl, 128, 512);
    tsplit_kernel<<<dim3(16, 16), dim3(32, 8), 0, s1>>>(W_gate, p_WgTh,  p_WgTl,  512, 512);
    hgemm2_kernel<<<dim3(DD/128, NT/128), 256, HG_SMEM, s1>>>(
        p_xh, p_xl, p_WgTh, p_WgTl, b_gate, p_gate, NT, DD, DD);
    cudaEventRecord(evG, s1);

    // ---- main stream: B-matrix path + scan ----
    wb_kernel<<<2048, 256>>>(W_site, b_site);
    tsplit_kernel<<<dim3(32, 16), dim3(32, 8)>>>(p_WB, p_WBTh, p_WBTl, 512, 1024);
    hgemm2_kernel<<<dim3(1024/128, NT/128), 256, HG_SMEM>>>(
        p_xh, p_xl, p_WBTh, p_WBTl, p_bB, p_Bmat, NT, 1024, DD);
    c_kernel<<<NT / 8, 256>>>(x);
    scan_kernel<<<BB, 32>>>(x);

    // join: site needed for M recovery, then final GEMM
    cudaStreamWaitEvent(0, evS, 0);
    mrec_kernel<<<NT, 128>>>();
    hgemm2_kernel<<<dim3(DD/128, NT/128), 256, HG_SMEM>>>(
        p_mh, p_ml, p_WcoTh, p_WcoTl, p_bco, p_y, NT, DD, 128);

    // join: gate needed for the epilogue
    cudaStreamWaitEvent(0, evG, 0);
    post_kernel<<<NT, 256>>>(x, gamma, beta, out);
}

// round 10
// speedup vs baseline: 1.2278x; 1.2278x over previous
#include <cuda_runtime.h>
#include <cuda_bf16.h>
#include <math.h>
#include <stdint.h>

// Problem dims
#define BB   4
#define LL   1024
#define DD   512
#define CHI  32
#define SS   4
#define NT   (BB*LL)          // 4096 tokens
#define CSC  (CHI*SS*CHI)     // 4096

// ---------------- scratch (__device__ globals, no allocs) ----------------
__device__ float g_site[(size_t)NT * CSC];       // x @ W_site + b_site     (64 MB)
__device__ float g_gate[(size_t)NT * DD];        // x @ W_gate + b_gate
__device__ float g_Bmat[(size_t)NT * CHI * CHI]; // B_t stored [t][r*32+l]
__device__ float g_WB[512 * 1024];               // pre-reduced site weights (fp32)
__device__ float g_bB[1024];                     // pre-reduced site bias
__device__ float g_c[(size_t)NT * CHI];          // c_t[r] = u_t @ B_t
__device__ float g_left[(size_t)NT * CHI];       // recorded left vectors
__device__ float g_y[(size_t)NT * DD];           // pre-LN y
__device__ float g_Wco[128 * 512];               // W_bridge @ W_out (fp32)
__device__ float g_bco[512];                     // b_bridge @ W_out + b_out

// pre-converted bf16 split operands
__device__ __nv_bfloat16 g_xh[(size_t)NT * DD],   g_xl[(size_t)NT * DD];
__device__ __nv_bfloat16 g_WsT_h[(size_t)CSC * DD], g_WsT_l[(size_t)CSC * DD];   // [n][k]
__device__ __nv_bfloat16 g_WgT_h[DD * DD],        g_WgT_l[DD * DD];
__device__ __nv_bfloat16 g_WBT_h[1024 * DD],      g_WBT_l[1024 * DD];
__device__ __nv_bfloat16 g_WcoT_h[DD * 128],      g_WcoT_l[DD * 128];
__device__ __nv_bfloat16 g_mh[(size_t)NT * 128],  g_ml[(size_t)NT * 128];

// ---------------- helpers ----------------
__device__ __forceinline__ uint32_t smem_u32(const void* p) {
    uint32_t a;
    asm("{ .reg .u64 t; cvta.to.shared.u64 t, %1; cvt.u32.u64 %0, t; }" : "=r"(a) : "l"(p));
    return a;
}
__device__ __forceinline__ void bsplit(float v, __nv_bfloat16& h, __nv_bfloat16& l)
{
    h = __float2bfloat16(v);
    l = __float2bfloat16(v - __bfloat162float(h));
}
#define CPA16(dst, src)  asm volatile("cp.async.cg.shared.global [%0], [%1], 16;" :: "r"(dst), "l"(src))
#define CPA_COMMIT()     asm volatile("cp.async.commit_group;" ::: "memory")
#define CPA_WAIT0()      asm volatile("cp.async.wait_group 0;" ::: "memory")
#define CPA_WAIT1()      asm volatile("cp.async.wait_group 1;" ::: "memory")

#define MMA_BF16(d, a0, a1, a2, a3, b0, b1)                                   \
    asm volatile("mma.sync.aligned.m16n8k16.row.col.f32.bf16.bf16.f32 "       \
                 "{%0,%1,%2,%3}, {%4,%5,%6,%7}, {%8,%9}, {%0,%1,%2,%3};\n"    \
                 : "+f"(d[0]), "+f"(d[1]), "+f"(d[2]), "+f"(d[3])             \
                 : "r"(a0), "r"(a1), "r"(a2), "r"(a3), "r"(b0), "r"(b1))

#define LDSM4(r, addr)                                                        \
    asm volatile("ldmatrix.sync.aligned.m8n8.x4.shared.b16 {%0,%1,%2,%3}, [%4];" \
                 : "=r"((r)[0]), "=r"((r)[1]), "=r"((r)[2]), "=r"((r)[3])     \
                 : "r"(addr))

// ---------------- x -> bf16 split ----------------
__global__ void xcvt_kernel(const float* __restrict__ x)
{
    int i = blockIdx.x * 256 + threadIdx.x;      // NT*DD = 2M
    __nv_bfloat16 h, l;
    bsplit(x[i], h, l);
    g_xh[i] = h; g_xl[i] = l;
}

// ---------------- transpose + split: src[K][N] fp32 -> dh/dl[N][K] bf16 ----
__global__ void tsplit_kernel(const float* __restrict__ src,
                              __nv_bfloat16* __restrict__ dh,
                              __nv_bfloat16* __restrict__ dl, int K, int N)
{
    __shared__ float t[32][33];
    int bn = blockIdx.x * 32, bk = blockIdx.y * 32;
    int tx = threadIdx.x, ty = threadIdx.y;
#pragma unroll
    for (int i = ty; i < 32; i += 8)
        t[i][tx] = src[(size_t)(bk + i) * N + bn + tx];
    __syncthreads();
#pragma unroll
    for (int i = ty; i < 32; i += 8) {
        __nv_bfloat16 h, l;
        bsplit(t[tx][i], h, l);                  // = src[bk+tx][bn+i]
        dh[(size_t)(bn + i) * K + bk + tx] = h;
        dl[(size_t)(bn + i) * K + bk + tx] = l;
    }
}

// ---------------- prep: fuse bridge+out weights (fp32) ----------------
__global__ void prep_kernel(const float* __restrict__ Wb, const float* __restrict__ bb,
                            const float* __restrict__ Wo, const float* __restrict__ bo)
{
    int idx = blockIdx.x * blockDim.x + threadIdx.x;   // 0..65535
    int pr = idx >> 9, j = idx & 511;
    float s = 0.f;
#pragma unroll
    for (int i = 0; i < 32; ++i)
        s = fmaf(Wb[pr * 32 + i], Wo[i * 512 + j], s);
    g_Wco[idx] = s;
    if (idx < 512) {
        float c = bo[idx];
#pragma unroll
        for (int i = 0; i < 32; ++i)
            c = fmaf(bb[i], Wo[i * 512 + idx], c);
        g_bco[idx] = c;
    }
}

// ---------------- reduce W_site over physical index -> W_B (fp32) ----------
__global__ __launch_bounds__(256) void wb_kernel(const float* __restrict__ Ws,
                                                 const float* __restrict__ bs)
{
    int idx = blockIdx.x * 256 + threadIdx.x;          // 0 .. 512*1024-1
    int d = idx >> 10, rem = idx & 1023;
    int l = rem >> 5, r = rem & 31;
    const float* p = Ws + (size_t)d * 4096 + l * 128 + r;   // coalesced in r
    g_WB[(size_t)d * 1024 + r * 32 + l] = p[0] + p[32] + p[64] + p[96];
    if (idx < 1024) {
        int ll = idx >> 5, rr = idx & 31;
        const float* q = bs + ll * 128 + rr;
        g_bB[rr * 32 + ll] = q[0] + q[32] + q[64] + q[96];
    }
}

// ============ bf16-split tensor GEMM: C = A[MxK] @ B[KxN] + bias ===========
#define HG_SMEM (2 * 40960)

__device__ __forceinline__ void hg_load(uint32_t sb,
    const __nv_bfloat16* __restrict__ Ah, const __nv_bfloat16* __restrict__ Al,
    const __nv_bfloat16* __restrict__ Bh, const __nv_bfloat16* __restrict__ Bl,
    int bm, int bn, int K, int k0, int tid)
{
#pragma unroll
    for (int q = 0; q < 2; ++q) {
        int id = tid + 256 * q;                  // 0..511
        int r = id >> 2, c = id & 3;
        uint32_t so = (uint32_t)(r * 80 + c * 16);
        size_t goA = (size_t)(bm + r) * K + k0 + c * 8;
        size_t goB = (size_t)(bn + r) * K + k0 + c * 8;
        CPA16(sb + so,          Ah + goA);
        CPA16(sb + 10240 + so,  Al + goA);
        CPA16(sb + 20480 + so,  Bh + goB);
        CPA16(sb + 30720 + so,  Bl + goB);
    }
}

__device__ __forceinline__ void hg_compute(uint32_t sb, float acc[4][4][4],
                                           int m0w, int n0w, int lane)
{
    const int arow = (lane & 15);
    const int acolb = (lane >> 4) * 16;
    const int brow = (lane & 7) + ((lane >> 4) << 3);
    const int bcolb = ((lane >> 3) & 1) * 16;
#pragma unroll
    for (int kk = 0; kk < 2; ++kk) {
        const int kb = kk * 32;                  // 16 bf16 = 32 bytes
        uint32_t ah[4][4], al[4][4], bh[2][4], bl[2][4];
#pragma unroll
        for (int mi = 0; mi < 4; ++mi) {
            uint32_t adr = sb + (uint32_t)((m0w + mi * 16 + arow) * 80 + kb + acolb);
            LDSM4(ah[mi], adr);
            LDSM4(al[mi], adr + 10240);
        }
#pragma unroll
        for (int np = 0; np < 2; ++np) {
            uint32_t adr = sb + 20480 + (uint32_t)((n0w + np * 16 + brow) * 80 + kb + bcolb);
            LDSM4(bh[np], adr);
            LDSM4(bl[np], adr + 10240);
        }
#pragma unroll
        for (int ni = 0; ni < 4; ++ni) {
            uint32_t h0 = bh[ni >> 1][(ni & 1) * 2], h1 = bh[ni >> 1][(ni & 1) * 2 + 1];
            uint32_t l0 = bl[ni >> 1][(ni & 1) * 2], l1 = bl[ni >> 1][(ni & 1) * 2 + 1];
#pragma unroll
            for (int mi = 0; mi < 4; ++mi) {
                MMA_BF16(acc[mi][ni], ah[mi][0], ah[mi][1], ah[mi][2], ah[mi][3], h0, h1);
                MMA_BF16(acc[mi][ni], ah[mi][0], ah[mi][1], ah[mi][2], ah[mi][3], l0, l1);
                MMA_BF16(acc[mi][ni], al[mi][0], al[mi][1], al[mi][2], al[mi][3], h0, h1);
            }
        }
    }
}

__global__ __launch_bounds__(256, 1)
void hgemm2_kernel(const __nv_bfloat16* __restrict__ Ah, const __nv_bfloat16* __restrict__ Al,
                   const __nv_bfloat16* __restrict__ Bh, const __nv_bfloat16* __restrict__ Bl,
                   const float* __restrict__ bias, float* __restrict__ C,
                   int M, int N, int K)
{
    extern __shared__ __align__(16) char smem[];
    const int tid = threadIdx.x;
    const int warp = tid >> 5, lane = tid & 31;
    const int g = lane >> 2, tg = lane & 3;
    const int m0w = (warp >> 2) * 64;            // 0 | 64
    const int n0w = (warp & 3) * 32;             // 0..96
    const int bm = blockIdx.y * 128, bn = blockIdx.x * 128;
    const uint32_t sb = smem_u32(smem);

    float acc[4][4][4];
#pragma unroll
    for (int i = 0; i < 4; ++i)
#pragma unroll
        for (int j = 0; j < 4; ++j)
#pragma unroll
            for (int e = 0; e < 4; ++e) acc[i][j][e] = 0.f;

    const int nk = K >> 5;
    hg_load(sb, Ah, Al, Bh, Bl, bm, bn, K, 0, tid);
    CPA_COMMIT();
    for (int i = 0; i < nk; ++i) {
        if (i + 1 < nk) {
            hg_load(sb + ((i + 1) & 1) * 40960, Ah, Al, Bh, Bl, bm, bn, K, (i + 1) * 32, tid);
            CPA_COMMIT();
            CPA_WAIT1();
        } else {
            CPA_WAIT0();
        }
        __syncthreads();
        hg_compute(sb + (uint32_t)((i & 1) * 40960), acc, m0w, n0w, lane);
        __syncthreads();
    }

#pragma unroll
    for (int mi = 0; mi < 4; ++mi) {
        int row = bm + m0w + mi * 16 + g;
#pragma unroll
        for (int ni = 0; ni < 4; ++ni) {
            int col = bn + n0w + ni * 8 + 2 * tg;
            float b0 = bias[col], b1 = bias[col + 1];
            *(float2*)&C[(size_t)row * N + col] =
                make_float2(acc[mi][ni][0] + b0, acc[mi][ni][1] + b1);
            *(float2*)&C[(size_t)(row + 8) * N + col] =
                make_float2(acc[mi][ni][2] + b0, acc[mi][ni][3] + b1);
        }
    }
}

// ---------------- c_t[r] = sum_l u_t[l] * B_t[l][r] (8 tokens/block) -------
__global__ __launch_bounds__(256) void c_kernel(const float* __restrict__ x)
{
    int t = blockIdx.x * 8 + (threadIdx.x >> 5);
    int r = threadIdx.x & 31;
    float u = x[(size_t)t * DD + r];           // lane l holds u_l
    const float* brow = g_Bmat + (size_t)t * 1024 + r * 32;
    float4 b4[8];
#pragma unroll
    for (int q = 0; q < 8; ++q) b4[q] = __ldg((const float4*)(brow + 4 * q));
    float c = 0.f;
#pragma unroll
    for (int q = 0; q < 8; ++q) {
        c = fmaf(__shfl_sync(0xffffffffu, u, 4 * q + 0), b4[q].x, c);
        c = fmaf(__shfl_sync(0xffffffffu, u, 4 * q + 1), b4[q].y, c);
        c = fmaf(__shfl_sync(0xffffffffu, u, 4 * q + 2), b4[q].z, c);
        c = fmaf(__shfl_sync(0xffffffffu, u, 4 * q + 3), b4[q].w, c);
    }
    g_c[(size_t)t * 32 + r] = c;
}

// ========== sequential scan: producer/consumer smem ring ==========
// Block = 160 threads: warp 0 = serial scan; warps 1-4 = cp.async producers
// filling a 20-stage ring (one stage = B tile 32x144B padded + c + u rows).
// Sync via volatile smem flags (generation = step+1) and a progress counter.
#define NS    20
#define STGB  4864                      // 32*144 + 128 (c) + 128 (u)
#define SCAN_SMEM (NS * STGB)

__device__ __forceinline__ float scan_step(float v, const float4* BC, float cc,
                                           float uu, float* leftp)
{
    float w0 = 0.f, w1 = 0.f, w2 = 0.f, w3 = 0.f;
    float s0 = 0.f, s1 = 0.f, s2 = 0.f, s3 = 0.f;
#pragma unroll
    for (int q = 0; q < 8; q += 4) {
        float va, vb, vc, vd;
        va = __shfl_sync(0xffffffffu, v, 4*q + 0);
        vb = __shfl_sync(0xffffffffu, v, 4*q + 1);
        vc = __shfl_sync(0xffffffffu, v, 4*q + 2);
        vd = __shfl_sync(0xffffffffu, v, 4*q + 3);
        w0 = fmaf(va, BC[q].x, w0); s0 = fmaf(va, va, s0);
        w0 = fmaf(vb, BC[q].y, w0); s0 = fmaf(vb, vb, s0);
        w0 = fmaf(vc, BC[q].z, w0); s0 = fmaf(vc, vc, s0);
        w0 = fmaf(vd, BC[q].w, w0); s0 = fmaf(vd, vd, s0);
        va = __shfl_sync(0xffffffffu, v, 4*q + 4);
        vb = __shfl_sync(0xffffffffu, v, 4*q + 5);
        vc = __shfl_sync(0xffffffffu, v, 4*q + 6);
        vd = __shfl_sync(0xffffffffu, v, 4*q + 7);
        w1 = fmaf(va, BC[q+1].x, w1); s1 = fmaf(va, va, s1);
        w1 = fmaf(vb, BC[q+1].y, w1); s1 = fmaf(vb, vb, s1);
        w1 = fmaf(vc, BC[q+1].z, w1); s1 = fmaf(vc, vc, s1);
        w1 = fmaf(vd, BC[q+1].w, w1); s1 = fmaf(vd, vd, s1);
        va = __shfl_sync(0xffffffffu, v, 4*q + 8);
        vb = __shfl_sync(0xffffffffu, v, 4*q + 9);
        vc = __shfl_sync(0xffffffffu, v, 4*q + 10);
        vd = __shfl_sync(0xffffffffu, v, 4*q + 11);
        w2 = fmaf(va, BC[q+2].x, w2); s2 = fmaf(va, va, s2);
        w2 = fmaf(vb, BC[q+2].y, w2); s2 = fmaf(vb, vb, s2);
        w2 = fmaf(vc, BC[q+2].z, w2); s2 = fmaf(vc, vc, s2);
        w2 = fmaf(vd, BC[q+2].w, w2); s2 = fmaf(vd, vd, s2);
        va = __shfl_sync(0xffffffffu, v, 4*q + 12);
        vb = __shfl_sync(0xffffffffu, v, 4*q + 13);
        vc = __shfl_sync(0xffffffffu, v, 4*q + 14);
        vd = __shfl_sync(0xffffffffu, v, 4*q + 15);
        w3 = fmaf(va, BC[q+3].x, w3); s3 = fmaf(va, va, s3);
        w3 = fmaf(vb, BC[q+3].y, w3); s3 = fmaf(vb, vb, s3);
        w3 = fmaf(vc, BC[q+3].z, w3); s3 = fmaf(vc, vc, s3);
        w3 = fmaf(vd, BC[q+3].w, w3); s3 = fmaf(vd, vd, s3);
    }
    float w = (w0 + w1) + (w2 + w3);
    float s = (s0 + s1) + (s2 + s3);
    float alpha = rsqrtf(s + 1e-24f);          // s==0 -> alpha*v == 0 == h0
    *leftp = fmaf(alpha, v, uu);
    return fmaf(alpha, w, cc);
}

__global__ __launch_bounds__(160, 1) void scan_kernel(const float* __restrict__ x)
{
    extern __shared__ __align__(16) char ring[];
    __shared__ volatile int flags[NS];
    __shared__ volatile int progress;

    const int b = blockIdx.x, tid = threadIdx.x;
    const int wid = tid >> 5, lane = tid & 31;
    const size_t tg0 = (size_t)b * LL;

    for (int i = tid; i < NS; i += 160) flags[i] = 0;
    if (tid == 0) progress = 0;
    __syncthreads();

    if (wid > 0) {
        // ---- producers: 4 warps, warp w handles steps s ≡ w-1 (mod 4) ----
        const int w = wid - 1;
        uint32_t rbase = smem_u32(ring);
        int slot = w;
        for (int s = w; s < LL; s += 4) {
            if (s >= NS) { while (progress < s - NS + 1) {} }
            uint32_t base = rbase + (uint32_t)slot * STGB;
            const char* gB = (const char*)(g_Bmat + (tg0 + s) * 1024);
#pragma unroll
            for (int q = 0; q < 8; ++q) {
                int i = lane + 32 * q;                       // 0..255 float4 chunks
                CPA16(base + (uint32_t)((i >> 3) * 144 + (i & 7) * 16), gB + i * 16);
            }
            if (lane < 8) {
                CPA16(base + 4608u + lane * 16,
                      (const char*)(g_c + (tg0 + s) * 32) + lane * 16);
            } else if (lane < 16) {
                CPA16(base + 4736u + (lane - 8) * 16,
                      (const char*)(x + (tg0 + s) * DD) + (lane - 8) * 16);
            }
            CPA_COMMIT();
            CPA_WAIT0();
            __threadfence_block();
            __syncwarp();
            if (lane == 0) flags[slot] = s + 1;
            slot += 4; if (slot >= NS) slot -= NS;
        }
    } else {
        // ---- consumer: the serial recurrence ----
        float v = 0.f;
        float* lp = g_left + tg0 * 32 + lane;
        int slot = 0;
#pragma unroll 1
        for (int t = 0; t < LL; ++t) {
            while (flags[slot] < t + 1) {}
            const char* stg = ring + (size_t)slot * STGB;
            const float4* br = (const float4*)(stg + lane * 144);
            float4 B[8];
#pragma unroll
            for (int q = 0; q < 8; ++q) B[q] = br[q];
            float cc = *(const float*)(stg + 4608 + 4 * lane);
            float uu = *(const float*)(stg + 4736 + 4 * lane);
            v = scan_step(v, B, cc, uu, lp);
            lp += 32;
            __syncwarp();
            if (lane == 0) progress = t + 1;
            if (++slot == NS) slot = 0;
        }
    }
}

// ------- recover Mt per token; emit bf16 split for the final GEMM ----------
__global__ __launch_bounds__(128) void mrec_kernel()
{
    __shared__ float sleft[32];
    int t = blockIdx.x, tid = threadIdx.x;
    if (tid < 32) sleft[tid] = g_left[(size_t)t * 32 + tid];
    __syncthreads();
    const float* row = g_site + (size_t)t * CSC;
    float m = 0.f;
#pragma unroll
    for (int l = 0; l < 32; ++l)
        m = fmaf(sleft[l], __ldcs(row + l * 128 + tid), m);   // streaming, coalesced
    __nv_bfloat16 h, lo;
    bsplit(m, h, lo);
    g_mh[(size_t)t * 128 + tid] = h;
    g_ml[(size_t)t * 128 + tid] = lo;
}

// ---------------- LayerNorm + sigmoid-gated residual ----------------
__global__ __launch_bounds__(256) void post_kernel(const float* __restrict__ x,
                                                   const float* __restrict__ gamma,
                                                   const float* __restrict__ beta,
                                                   float* __restrict__ out)
{
    __shared__ float red[256];
    int t = blockIdx.x, tid = threadIdx.x;
    size_t base = (size_t)t * DD;
    int j0 = tid, j1 = tid + 256;
    float y0 = g_y[base + j0], y1 = g_y[base + j1];

    red[tid] = y0 + y1;
    __syncthreads();
    for (int st = 128; st > 0; st >>= 1) {
        if (tid < st) red[tid] += red[tid + st];
        __syncthreads();
    }
    float mu = red[0] * (1.f / 512.f);
    __syncthreads();

    float d0 = y0 - mu, d1 = y1 - mu;
    red[tid] = d0 * d0 + d1 * d1;
    __syncthreads();
    for (int st = 128; st > 0; st >>= 1) {
        if (tid < st) red[tid] += red[tid + st];
        __syncthreads();
    }
    float var = red[0] * (1.f / 512.f);
    float rstd = rsqrtf(var + 1e-6f);

    float yn0 = d0 * rstd * gamma[j0] + beta[j0];
    float yn1 = d1 * rstd * gamma[j1] + beta[j1];
    float gl0 = g_gate[base + j0], gl1 = g_gate[base + j1];
    float gt0 = 1.f / (1.f + expf(-gl0));
    float gt1 = 1.f / (1.f + expf(-gl1));
    float xv0 = x[base + j0], xv1 = x[base + j1];
    out[base + j0] = gt0 * yn0 + (1.f - gt0) * xv0;
    out[base + j1] = gt1 * yn1 + (1.f - gt1) * xv1;
}

// ---------------- launch ----------------
extern "C" void kernel_launch(void* const* d_in, const int* in_sizes, int n_in,
                              void* d_out, int out_size)
{
    (void)in_sizes; (void)n_in; (void)out_size;
    const float* x       = (const float*)d_in[0];
    const float* W_site  = (const float*)d_in[1];
    const float* b_site  = (const float*)d_in[2];
    const float* W_bridge= (const float*)d_in[3];
    const float* b_bridge= (const float*)d_in[4];
    const float* W_out   = (const float*)d_in[5];
    const float* b_out   = (const float*)d_in[6];
    const float* gamma   = (const float*)d_in[7];
    const float* beta    = (const float*)d_in[8];
    const float* W_gate  = (const float*)d_in[9];
    const float* b_gate  = (const float*)d_in[10];
    float* out = (float*)d_out;

    static float *p_site, *p_gate, *p_y, *p_WB, *p_bB, *p_Wco, *p_bco, *p_Bmat;
    static __nv_bfloat16 *p_xh, *p_xl, *p_WsTh, *p_WsTl, *p_WgTh, *p_WgTl,
                         *p_WBTh, *p_WBTl, *p_WcoTh, *p_WcoTl, *p_mh, *p_ml;
    static cudaStream_t s1;
    static cudaEvent_t ev0, evS, evG;
    static bool inited = false;
    if (!inited) {
        cudaGetSymbolAddress((void**)&p_site,  g_site);
        cudaGetSymbolAddress((void**)&p_gate,  g_gate);
        cudaGetSymbolAddress((void**)&p_y,     g_y);
        cudaGetSymbolAddress((void**)&p_WB,    g_WB);
        cudaGetSymbolAddress((void**)&p_bB,    g_bB);
        cudaGetSymbolAddress((void**)&p_Wco,   g_Wco);
        cudaGetSymbolAddress((void**)&p_bco,   g_bco);
        cudaGetSymbolAddress((void**)&p_Bmat,  g_Bmat);
        cudaGetSymbolAddress((void**)&p_xh,    g_xh);
        cudaGetSymbolAddress((void**)&p_xl,    g_xl);
        cudaGetSymbolAddress((void**)&p_WsTh,  g_WsT_h);
        cudaGetSymbolAddress((void**)&p_WsTl,  g_WsT_l);
        cudaGetSymbolAddress((void**)&p_WgTh,  g_WgT_h);
        cudaGetSymbolAddress((void**)&p_WgTl,  g_WgT_l);
        cudaGetSymbolAddress((void**)&p_WBTh,  g_WBT_h);
        cudaGetSymbolAddress((void**)&p_WBTl,  g_WBT_l);
        cudaGetSymbolAddress((void**)&p_WcoTh, g_WcoT_h);
        cudaGetSymbolAddress((void**)&p_WcoTl, g_WcoT_l);
        cudaGetSymbolAddress((void**)&p_mh,    g_mh);
        cudaGetSymbolAddress((void**)&p_ml,    g_ml);
        cudaStreamCreateWithFlags(&s1, cudaStreamNonBlocking);
        cudaEventCreateWithFlags(&ev0, cudaEventDisableTiming);
        cudaEventCreateWithFlags(&evS, cudaEventDisableTiming);
        cudaEventCreateWithFlags(&evG, cudaEventDisableTiming);
        cudaFuncSetAttribute(hgemm2_kernel, cudaFuncAttributeMaxDynamicSharedMemorySize, HG_SMEM);
        cudaFuncSetAttribute(scan_kernel, cudaFuncAttributeMaxDynamicSharedMemorySize, SCAN_SMEM);
        inited = true;
    }

    // shared prologue: x split (both branches need it)
    xcvt_kernel<<<(NT * DD) / 256, 256>>>(x);
    cudaEventRecord(ev0, 0);
    cudaStreamWaitEvent(s1, ev0, 0);

    // ---- side stream: site GEMM first, then gate ----
    tsplit_kernel<<<dim3(128,16), dim3(32, 8), 0, s1>>>(W_site, p_WsTh, p_WsTl, 512, 4096);
    prep_kernel<<<256, 256, 0, s1>>>(W_bridge, b_bridge, W_out, b_out);
    hgemm2_kernel<<<dim3(CSC/128, NT/128), 256, HG_SMEM, s1>>>(
        p_xh, p_xl, p_WsTh, p_WsTl, b_site, p_site, NT, CSC, DD);
    cudaEventRecord(evS, s1);
    tsplit_kernel<<<dim3(16, 4),  dim3(32, 8), 0, s1>>>(p_Wco,  p_WcoTh, p_WcoTl, 128, 512);
    tsplit_kernel<<<dim3(16, 16), dim3(32, 8), 0, s1>>>(W_gate, p_WgTh,  p_WgTl,  512, 512);
    hgemm2_kernel<<<dim3(DD/128, NT/128), 256, HG_SMEM, s1>>>(
        p_xh, p_xl, p_WgTh, p_WgTl, b_gate, p_gate, NT, DD, DD);
    cudaEventRecord(evG, s1);

    // ---- main stream: B-matrix path + ring-buffered scan ----
    wb_kernel<<<2048, 256>>>(W_site, b_site);
    tsplit_kernel<<<dim3(32, 16), dim3(32, 8)>>>(p_WB, p_WBTh, p_WBTl, 512, 1024);
    hgemm2_kernel<<<dim3(1024/128, NT/128), 256, HG_SMEM>>>(
        p_xh, p_xl, p_WBTh, p_WBTl, p_bB, p_Bmat, NT, 1024, DD);
    c_kernel<<<NT / 8, 256>>>(x);
    scan_kernel<<<BB, 160, SCAN_SMEM>>>(x);

    // join: site needed for M recovery, then final GEMM
    cudaStreamWaitEvent(0, evS, 0);
    mrec_kernel<<<NT, 128>>>();
    hgemm2_kernel<<<dim3(DD/128, NT/128), 256, HG_SMEM>>>(
        p_mh, p_ml, p_WcoTh, p_WcoTl, p_bco, p_y, NT, DD, 128);

    // join: gate needed for the epilogue
    cudaStreamWaitEvent(0, evG, 0);
    post_kernel<<<NT, 256>>>(x, gamma, beta, out);
}

// round 13
// speedup vs baseline: 1.2439x; 1.0131x over previous
#include <cuda_runtime.h>
#include <cuda_bf16.h>
#include <math.h>
#include <stdint.h>

// Problem dims
#define BB   4
#define LL   1024
#define DD   512
#define CHI  32
#define SS   4
#define NT   (BB*LL)          // 4096 tokens
#define CSC  (CHI*SS*CHI)     // 4096

// ---------------- scratch (__device__ globals, no allocs) ----------------
__device__ float g_site[(size_t)NT * CSC];       // x @ W_site + b_site     (64 MB)
__device__ float g_gate[(size_t)NT * DD];        // x @ W_gate + b_gate
__device__ float g_Bmat[(size_t)NT * CHI * CHI]; // B_t stored [t][r*32+l]
__device__ float g_WB[512 * 1024];               // pre-reduced site weights (fp32)
__device__ float g_bB[1024];                     // pre-reduced site bias
__device__ float g_c[(size_t)NT * CHI];          // c_t[r] = u_t @ B_t
__device__ float g_left[(size_t)NT * CHI];       // recorded left vectors
__device__ float g_y[(size_t)NT * DD];           // pre-LN y
__device__ float g_Wco[128 * 512];               // W_bridge @ W_out (fp32)
__device__ float g_bco[512];                     // b_bridge @ W_out + b_out

// pre-converted bf16 split operands
__device__ __nv_bfloat16 g_xh[(size_t)NT * DD],   g_xl[(size_t)NT * DD];
__device__ __nv_bfloat16 g_WsT_h[(size_t)CSC * DD], g_WsT_l[(size_t)CSC * DD];   // [n][k]
__device__ __nv_bfloat16 g_WgT_h[DD * DD],        g_WgT_l[DD * DD];
__device__ __nv_bfloat16 g_WBT_h[1024 * DD],      g_WBT_l[1024 * DD];
__device__ __nv_bfloat16 g_WcoT_h[DD * 128],      g_WcoT_l[DD * 128];
__device__ __nv_bfloat16 g_mh[(size_t)NT * 128],  g_ml[(size_t)NT * 128];

// ---------------- helpers ----------------
__device__ __forceinline__ uint32_t smem_u32(const void* p) {
    uint32_t a;
    asm("{ .reg .u64 t; cvta.to.shared.u64 t, %1; cvt.u32.u64 %0, t; }" : "=r"(a) : "l"(p));
    return a;
}
__device__ __forceinline__ void bsplit(float v, __nv_bfloat16& h, __nv_bfloat16& l)
{
    h = __float2bfloat16(v);
    l = __float2bfloat16(v - __bfloat162float(h));
}
#define CPA16(dst, src)  asm volatile("cp.async.cg.shared.global [%0], [%1], 16;" :: "r"(dst), "l"(src))
#define CPA_COMMIT()     asm volatile("cp.async.commit_group;" ::: "memory")
#define CPA_WAIT0()      asm volatile("cp.async.wait_group 0;" ::: "memory")
#define CPA_WAIT1()      asm volatile("cp.async.wait_group 1;" ::: "memory")

#define MMA_BF16(d, a0, a1, a2, a3, b0, b1)                                   \
    asm volatile("mma.sync.aligned.m16n8k16.row.col.f32.bf16.bf16.f32 "       \
                 "{%0,%1,%2,%3}, {%4,%5,%6,%7}, {%8,%9}, {%0,%1,%2,%3};\n"    \
                 : "+f"(d[0]), "+f"(d[1]), "+f"(d[2]), "+f"(d[3])             \
                 : "r"(a0), "r"(a1), "r"(a2), "r"(a3), "r"(b0), "r"(b1))

#define LDSM4(r, addr)                                                        \
    asm volatile("ldmatrix.sync.aligned.m8n8.x4.shared.b16 {%0,%1,%2,%3}, [%4];" \
                 : "=r"((r)[0]), "=r"((r)[1]), "=r"((r)[2]), "=r"((r)[3])     \
                 : "r"(addr))

// ---------------- x -> bf16 split ----------------
__global__ void xcvt_kernel(const float* __restrict__ x)
{
    int i = blockIdx.x * 256 + threadIdx.x;      // NT*DD = 2M
    __nv_bfloat16 h, l;
    bsplit(x[i], h, l);
    g_xh[i] = h; g_xl[i] = l;
}

// ---------------- transpose + split: src[K][N] fp32 -> dh/dl[N][K] bf16 ----
__global__ void tsplit_kernel(const float* __restrict__ src,
                              __nv_bfloat16* __restrict__ dh,
                              __nv_bfloat16* __restrict__ dl, int K, int N)
{
    __shared__ float t[32][33];
    int bn = blockIdx.x * 32, bk = blockIdx.y * 32;
    int tx = threadIdx.x, ty = threadIdx.y;
#pragma unroll
    for (int i = ty; i < 32; i += 8)
        t[i][tx] = src[(size_t)(bk + i) * N + bn + tx];
    __syncthreads();
#pragma unroll
    for (int i = ty; i < 32; i += 8) {
        __nv_bfloat16 h, l;
        bsplit(t[tx][i], h, l);                  // = src[bk+tx][bn+i]
        dh[(size_t)(bn + i) * K + bk + tx] = h;
        dl[(size_t)(bn + i) * K + bk + tx] = l;
    }
}

// ---------------- prep: fuse bridge+out weights (fp32) ----------------
__global__ void prep_kernel(const float* __restrict__ Wb, const float* __restrict__ bb,
                            const float* __restrict__ Wo, const float* __restrict__ bo)
{
    int idx = blockIdx.x * blockDim.x + threadIdx.x;   // 0..65535
    int pr = idx >> 9, j = idx & 511;
    float s = 0.f;
#pragma unroll
    for (int i = 0; i < 32; ++i)
        s = fmaf(Wb[pr * 32 + i], Wo[i * 512 + j], s);
    g_Wco[idx] = s;
    if (idx < 512) {
        float c = bo[idx];
#pragma unroll
        for (int i = 0; i < 32; ++i)
            c = fmaf(bb[i], Wo[i * 512 + idx], c);
        g_bco[idx] = c;
    }
}

// ---------------- reduce W_site over physical index -> W_B (fp32) ----------
__global__ __launch_bounds__(256) void wb_kernel(const float* __restrict__ Ws,
                                                 const float* __restrict__ bs)
{
    int idx = blockIdx.x * 256 + threadIdx.x;          // 0 .. 512*1024-1
    int d = idx >> 10, rem = idx & 1023;
    int l = rem >> 5, r = rem & 31;
    const float* p = Ws + (size_t)d * 4096 + l * 128 + r;   // coalesced in r
    g_WB[(size_t)d * 1024 + r * 32 + l] = p[0] + p[32] + p[64] + p[96];
    if (idx < 1024) {
        int ll = idx >> 5, rr = idx & 31;
        const float* q = bs + ll * 128 + rr;
        g_bB[rr * 32 + ll] = q[0] + q[32] + q[64] + q[96];
    }
}

// ============ bf16-split tensor GEMM: C = A[MxK] @ B[KxN] + bias ===========
#define HG_SMEM (2 * 40960)

__device__ __forceinline__ void hg_load(uint32_t sb,
    const __nv_bfloat16* __restrict__ Ah, const __nv_bfloat16* __restrict__ Al,
    const __nv_bfloat16* __restrict__ Bh, const __nv_bfloat16* __restrict__ Bl,
    int bm, int bn, int K, int k0, int tid)
{
#pragma unroll
    for (int q = 0; q < 2; ++q) {
        int id = tid + 256 * q;                  // 0..511
        int r = id >> 2, c = id & 3;
        uint32_t so = (uint32_t)(r * 80 + c * 16);
        size_t goA = (size_t)(bm + r) * K + k0 + c * 8;
        size_t goB = (size_t)(bn + r) * K + k0 + c * 8;
        CPA16(sb + so,          Ah + goA);
        CPA16(sb + 10240 + so,  Al + goA);
        CPA16(sb + 20480 + so,  Bh + goB);
        CPA16(sb + 30720 + so,  Bl + goB);
    }
}

__device__ __forceinline__ void hg_compute(uint32_t sb, float acc[4][4][4],
                                           int m0w, int n0w, int lane)
{
    const int arow = (lane & 15);
    const int acolb = (lane >> 4) * 16;
    const int brow = (lane & 7) + ((lane >> 4) << 3);
    const int bcolb = ((lane >> 3) & 1) * 16;
#pragma unroll
    for (int kk = 0; kk < 2; ++kk) {
        const int kb = kk * 32;                  // 16 bf16 = 32 bytes
        uint32_t ah[4][4], al[4][4], bh[2][4], bl[2][4];
#pragma unroll
        for (int mi = 0; mi < 4; ++mi) {
            uint32_t adr = sb + (uint32_t)((m0w + mi * 16 + arow) * 80 + kb + acolb);
            LDSM4(ah[mi], adr);
            LDSM4(al[mi], adr + 10240);
        }
#pragma unroll
        for (int np = 0; np < 2; ++np) {
            uint32_t adr = sb + 20480 + (uint32_t)((n0w + np * 16 + brow) * 80 + kb + bcolb);
            LDSM4(bh[np], adr);
            LDSM4(bl[np], adr + 10240);
        }
#pragma unroll
        for (int ni = 0; ni < 4; ++ni) {
            uint32_t h0 = bh[ni >> 1][(ni & 1) * 2], h1 = bh[ni >> 1][(ni & 1) * 2 + 1];
            uint32_t l0 = bl[ni >> 1][(ni & 1) * 2], l1 = bl[ni >> 1][(ni & 1) * 2 + 1];
#pragma unroll
            for (int mi = 0; mi < 4; ++mi) {
                MMA_BF16(acc[mi][ni], ah[mi][0], ah[mi][1], ah[mi][2], ah[mi][3], h0, h1);
                MMA_BF16(acc[mi][ni], ah[mi][0], ah[mi][1], ah[mi][2], ah[mi][3], l0, l1);
                MMA_BF16(acc[mi][ni], al[mi][0], al[mi][1], al[mi][2], al[mi][3], h0, h1);
            }
        }
    }
}

__global__ __launch_bounds__(256, 1)
void hgemm2_kernel(const __nv_bfloat16* __restrict__ Ah, const __nv_bfloat16* __restrict__ Al,
                   const __nv_bfloat16* __restrict__ Bh, const __nv_bfloat16* __restrict__ Bl,
                   const float* __restrict__ bias, float* __restrict__ C,
                   int M, int N, int K)
{
    extern __shared__ __align__(16) char smem[];
    const int tid = threadIdx.x;
    const int warp = tid >> 5, lane = tid & 31;
    const int g = lane >> 2, tg = lane & 3;
    const int m0w = (warp >> 2) * 64;            // 0 | 64
    const int n0w = (warp & 3) * 32;             // 0..96
    const int bm = blockIdx.y * 128, bn = blockIdx.x * 128;
    const uint32_t sb = smem_u32(smem);

    float acc[4][4][4];
#pragma unroll
    for (int i = 0; i < 4; ++i)
#pragma unroll
        for (int j = 0; j < 4; ++j)
#pragma unroll
            for (int e = 0; e < 4; ++e) acc[i][j][e] = 0.f;

    const int nk = K >> 5;
    hg_load(sb, Ah, Al, Bh, Bl, bm, bn, K, 0, tid);
    CPA_COMMIT();
    for (int i = 0; i < nk; ++i) {
        if (i + 1 < nk) {
            hg_load(sb + ((i + 1) & 1) * 40960, Ah, Al, Bh, Bl, bm, bn, K, (i + 1) * 32, tid);
            CPA_COMMIT();
            CPA_WAIT1();
        } else {
            CPA_WAIT0();
        }
        __syncthreads();
        hg_compute(sb + (uint32_t)((i & 1) * 40960), acc, m0w, n0w, lane);
        __syncthreads();
    }

#pragma unroll
    for (int mi = 0; mi < 4; ++mi) {
        int row = bm + m0w + mi * 16 + g;
#pragma unroll
        for (int ni = 0; ni < 4; ++ni) {
            int col = bn + n0w + ni * 8 + 2 * tg;
            float b0 = bias[col], b1 = bias[col + 1];
            *(float2*)&C[(size_t)row * N + col] =
                make_float2(acc[mi][ni][0] + b0, acc[mi][ni][1] + b1);
            *(float2*)&C[(size_t)(row + 8) * N + col] =
                make_float2(acc[mi][ni][2] + b0, acc[mi][ni][3] + b1);
        }
    }
}

// ---------------- c_t[r] = sum_l u_t[l] * B_t[l][r] (8 tokens/block) -------
__global__ __launch_bounds__(256) void c_kernel(const float* __restrict__ x)
{
    int t = blockIdx.x * 8 + (threadIdx.x >> 5);
    int r = threadIdx.x & 31;
    float u = x[(size_t)t * DD + r];           // lane l holds u_l
    const float* brow = g_Bmat + (size_t)t * 1024 + r * 32;
    float4 b4[8];
#pragma unroll
    for (int q = 0; q < 8; ++q) b4[q] = __ldg((const float4*)(brow + 4 * q));
    float c = 0.f;
#pragma unroll
    for (int q = 0; q < 8; ++q) {
        c = fmaf(__shfl_sync(0xffffffffu, u, 4 * q + 0), b4[q].x, c);
        c = fmaf(__shfl_sync(0xffffffffu, u, 4 * q + 1), b4[q].y, c);
        c = fmaf(__shfl_sync(0xffffffffu, u, 4 * q + 2), b4[q].z, c);
        c = fmaf(__shfl_sync(0xffffffffu, u, 4 * q + 3), b4[q].w, c);
    }
    g_c[(size_t)t * 32 + r] = c;
}

// ========== sequential scan: producer/consumer smem ring ==========
// Block = 288 threads (9 warps): warps 0-7 = cp.async producers (depth-2
// pipelined, 16 step-loads in flight); warp 8 = serial consumer (highest wid
// -> wins the hi-wid-first arbiter against spinning producers).
#define NS    24
#define STGB  4864                      // 32*144 + 128 (c) + 128 (u)
#define SCAN_SMEM (NS * STGB)
#define NPROD 8

__device__ __forceinline__ float scan_step(float v, const float4* BC, float cc,
                                           float uu, float* leftp)
{
    // 8 independent w-chains + 8 s-chains (depth 4) off the same broadcasts
    float w[8], s[8];
#pragma unroll
    for (int q = 0; q < 8; ++q) {
        float va = __shfl_sync(0xffffffffu, v, 4*q + 0);
        float vb = __shfl_sync(0xffffffffu, v, 4*q + 1);
        float vc = __shfl_sync(0xffffffffu, v, 4*q + 2);
        float vd = __shfl_sync(0xffffffffu, v, 4*q + 3);
        float wq, sq;
        wq = va * BC[q].x;          sq = va * va;
        wq = fmaf(vb, BC[q].y, wq); sq = fmaf(vb, vb, sq);
        wq = fmaf(vc, BC[q].z, wq); sq = fmaf(vc, vc, sq);
        wq = fmaf(vd, BC[q].w, wq); sq = fmaf(vd, vd, sq);
        w[q] = wq; s[q] = sq;
    }
    float wt = ((w[0] + w[1]) + (w[2] + w[3])) + ((w[4] + w[5]) + (w[6] + w[7]));
    float st = ((s[0] + s[1]) + (s[2] + s[3])) + ((s[4] + s[5]) + (s[6] + s[7]));
    float alpha = rsqrtf(st + 1e-24f);          // s==0 -> alpha*v == 0 == h0
    *leftp = fmaf(alpha, v, uu);
    return fmaf(alpha, wt, cc);
}

__device__ __forceinline__ void prod_issue(uint32_t base, size_t tg0, int s,
                                           int lane, const float* __restrict__ x)
{
    const char* gB = (const char*)(g_Bmat + (tg0 + s) * 1024);
#pragma unroll
    for (int q = 0; q < 8; ++q) {
        int i = lane + 32 * q;                       // 0..255 float4 chunks
        CPA16(base + (uint32_t)((i >> 3) * 144 + (i & 7) * 16), gB + i * 16);
    }
    if (lane < 8) {
        CPA16(base + 4608u + lane * 16,
              (const char*)(g_c + (tg0 + s) * 32) + lane * 16);
    } else if (lane < 16) {
        CPA16(base + 4736u + (lane - 8) * 16,
              (const char*)(x + (tg0 + s) * DD) + (lane - 8) * 16);
    }
}

__global__ __launch_bounds__(32 * (NPROD + 1), 1) void scan_kernel(const float* __restrict__ x)
{
    extern __shared__ __align__(16) char ring[];
    __shared__ volatile int flags[NS];
    __shared__ volatile int progress;

    const int b = blockIdx.x, tid = threadIdx.x;
    const int wid = tid >> 5, lane = tid & 31;
    const size_t tg0 = (size_t)b * LL;

    for (int i = tid; i < NS; i += 32 * (NPROD + 1)) flags[i] = 0;
    if (tid == 0) progress = 0;
    __syncthreads();

    if (wid < NPROD) {
        // ---- producers: warp w handles steps s ≡ w (mod NPROD), depth-2 ----
        const int w = wid;
        uint32_t rbase = smem_u32(ring);
        int s = w;
        prod_issue(rbase + (uint32_t)(s % NS) * STGB, tg0, s, lane, x);
        CPA_COMMIT();
        for (int next = s + NPROD; next < LL; next += NPROD) {
            if (next >= NS) { while (progress < next - NS + 1) {} }
            prod_issue(rbase + (uint32_t)(next % NS) * STGB, tg0, next, lane, x);
            CPA_COMMIT();
            CPA_WAIT1();                      // oldest group (step s) done
            __threadfence_block();
            __syncwarp();
            if (lane == 0) flags[s % NS] = s + 1;
            s = next;
        }
        CPA_WAIT0();
        __threadfence_block();
        __syncwarp();
        if (lane == 0) flags[s % NS] = s + 1;
    } else {
        // ---- consumer (highest wid): the serial recurrence ----
        float v = 0.f;
        float* lp = g_left + tg0 * 32 + lane;
        int slot = 0;
#pragma unroll 1
        for (int t = 0; t < LL; ++t) {
            while (flags[slot] < t + 1) {}
            const char* stg = ring + (size_t)slot * STGB;
            const float4* br = (const float4*)(stg + lane * 144);
            float4 B[8];
#pragma unroll
            for (int q = 0; q < 8; ++q) B[q] = br[q];
            float cc = *(const float*)(stg + 4608 + 4 * lane);
            float uu = *(const float*)(stg + 4736 + 4 * lane);
            v = scan_step(v, B, cc, uu, lp);
            lp += 32;
            __syncwarp();
            if (lane == 0) progress = t + 1;
            if (++slot == NS) slot = 0;
        }
    }
}

// ------- recover Mt per token; emit bf16 split for the final GEMM ----------
__global__ __launch_bounds__(128) void mrec_kernel()
{
    __shared__ float sleft[32];
    int t = blockIdx.x, tid = threadIdx.x;
    if (tid < 32) sleft[tid] = g_left[(size_t)t * 32 + tid];
    __syncthreads();
    const float* row = g_site + (size_t)t * CSC;
    float m = 0.f;
#pragma unroll
    for (int l = 0; l < 32; ++l)
        m = fmaf(sleft[l], __ldcs(row + l * 128 + tid), m);   // streaming, coalesced
    __nv_bfloat16 h, lo;
    bsplit(m, h, lo);
    g_mh[(size_t)t * 128 + tid] = h;
    g_ml[(size_t)t * 128 + tid] = lo;
}

// ---------------- LayerNorm + sigmoid-gated residual ----------------
__global__ __launch_bounds__(256) void post_kernel(const float* __restrict__ x,
                                                   const float* __restrict__ gamma,
                                                   const float* __restrict__ beta,
                                                   float* __restrict__ out)
{
    __shared__ float red[256];
    int t = blockIdx.x, tid = threadIdx.x;
    size_t base = (size_t)t * DD;
    int j0 = tid, j1 = tid + 256;
    float y0 = g_y[base + j0], y1 = g_y[base + j1];

    red[tid] = y0 + y1;
    __syncthreads();
    for (int st = 128; st > 0; st >>= 1) {
        if (tid < st) red[tid] += red[tid + st];
        __syncthreads();
    }
    float mu = red[0] * (1.f / 512.f);
    __syncthreads();

    float d0 = y0 - mu, d1 = y1 - mu;
    red[tid] = d0 * d0 + d1 * d1;
    __syncthreads();
    for (int st = 128; st > 0; st >>= 1) {
        if (tid < st) red[tid] += red[tid + st];
        __syncthreads();
    }
    float var = red[0] * (1.f / 512.f);
    float rstd = rsqrtf(var + 1e-6f);

    float yn0 = d0 * rstd * gamma[j0] + beta[j0];
    float yn1 = d1 * rstd * gamma[j1] + beta[j1];
    float gl0 = g_gate[base + j0], gl1 = g_gate[base + j1];
    float gt0 = 1.f / (1.f + expf(-gl0));
    float gt1 = 1.f / (1.f + expf(-gl1));
    float xv0 = x[base + j0], xv1 = x[base + j1];
    out[base + j0] = gt0 * yn0 + (1.f - gt0) * xv0;
    out[base + j1] = gt1 * yn1 + (1.f - gt1) * xv1;
}

// ---------------- launch ----------------
extern "C" void kernel_launch(void* const* d_in, const int* in_sizes, int n_in,
                              void* d_out, int out_size)
{
    (void)in_sizes; (void)n_in; (void)out_size;
    const float* x       = (const float*)d_in[0];
    const float* W_site  = (const float*)d_in[1];
    const float* b_site  = (const float*)d_in[2];
    const float* W_bridge= (const float*)d_in[3];
    const float* b_bridge= (const float*)d_in[4];
    const float* W_out   = (const float*)d_in[5];
    const float* b_out   = (const float*)d_in[6];
    const float* gamma   = (const float*)d_in[7];
    const float* beta    = (const float*)d_in[8];
    const float* W_gate  = (const float*)d_in[9];
    const float* b_gate  = (const float*)d_in[10];
    float* out = (float*)d_out;

    static float *p_site, *p_gate, *p_y, *p_WB, *p_bB, *p_Wco, *p_bco, *p_Bmat;
    static __nv_bfloat16 *p_xh, *p_xl, *p_WsTh, *p_WsTl, *p_WgTh, *p_WgTl,
                         *p_WBTh, *p_WBTl, *p_WcoTh, *p_WcoTl, *p_mh, *p_ml;
    static cudaStream_t s1;
    static cudaEvent_t ev0, evS, evG;
    static bool inited = false;
    if (!inited) {
        cudaGetSymbolAddress((void**)&p_site,  g_site);
        cudaGetSymbolAddress((void**)&p_gate,  g_gate);
        cudaGetSymbolAddress((void**)&p_y,     g_y);
        cudaGetSymbolAddress((void**)&p_WB,    g_WB);
        cudaGetSymbolAddress((void**)&p_bB,    g_bB);
        cudaGetSymbolAddress((void**)&p_Wco,   g_Wco);
        cudaGetSymbolAddress((void**)&p_bco,   g_bco);
        cudaGetSymbolAddress((void**)&p_Bmat,  g_Bmat);
        cudaGetSymbolAddress((void**)&p_xh,    g_xh);
        cudaGetSymbolAddress((void**)&p_xl,    g_xl);
        cudaGetSymbolAddress((void**)&p_WsTh,  g_WsT_h);
        cudaGetSymbolAddress((void**)&p_WsTl,  g_WsT_l);
        cudaGetSymbolAddress((void**)&p_WgTh,  g_WgT_h);
        cudaGetSymbolAddress((void**)&p_WgTl,  g_WgT_l);
        cudaGetSymbolAddress((void**)&p_WBTh,  g_WBT_h);
        cudaGetSymbolAddress((void**)&p_WBTl,  g_WBT_l);
        cudaGetSymbolAddress((void**)&p_WcoTh, g_WcoT_h);
        cudaGetSymbolAddress((void**)&p_WcoTl, g_WcoT_l);
        cudaGetSymbolAddress((void**)&p_mh,    g_mh);
        cudaGetSymbolAddress((void**)&p_ml,    g_ml);
        cudaStreamCreateWithFlags(&s1, cudaStreamNonBlocking);
        cudaEventCreateWithFlags(&ev0, cudaEventDisableTiming);
        cudaEventCreateWithFlags(&evS, cudaEventDisableTiming);
        cudaEventCreateWithFlags(&evG, cudaEventDisableTiming);
        cudaFuncSetAttribute(hgemm2_kernel, cudaFuncAttributeMaxDynamicSharedMemorySize, HG_SMEM);
        cudaFuncSetAttribute(scan_kernel, cudaFuncAttributeMaxDynamicSharedMemorySize, SCAN_SMEM);
        inited = true;
    }

    // shared prologue: x split (both branches need it)
    xcvt_kernel<<<(NT * DD) / 256, 256>>>(x);
    cudaEventRecord(ev0, 0);
    cudaStreamWaitEvent(s1, ev0, 0);

    // ---- side stream: site GEMM first, then gate ----
    tsplit_kernel<<<dim3(128,16), dim3(32, 8), 0, s1>>>(W_site, p_WsTh, p_WsTl, 512, 4096);
    prep_kernel<<<256, 256, 0, s1>>>(W_bridge, b_bridge, W_out, b_out);
    hgemm2_kernel<<<dim3(CSC/128, NT/128), 256, HG_SMEM, s1>>>(
        p_xh, p_xl, p_WsTh, p_WsTl, b_site, p_site, NT, CSC, DD);
    cudaEventRecord(evS, s1);
    tsplit_kernel<<<dim3(16, 4),  dim3(32, 8), 0, s1>>>(p_Wco,  p_WcoTh, p_WcoTl, 128, 512);
    tsplit_kernel<<<dim3(16, 16), dim3(32, 8), 0, s1>>>(W_gate, p_WgTh,  p_WgTl,  512, 512);
    hgemm2_kernel<<<dim3(DD/128, NT/128), 256, HG_SMEM, s1>>>(
        p_xh, p_xl, p_WgTh, p_WgTl, b_gate, p_gate, NT, DD, DD);
    cudaEventRecord(evG, s1);

    // ---- main stream: B-matrix path + ring-buffered scan ----
    wb_kernel<<<2048, 256>>>(W_site, b_site);
    tsplit_kernel<<<dim3(32, 16), dim3(32, 8)>>>(p_WB, p_WBTh, p_WBTl, 512, 1024);
    hgemm2_kernel<<<dim3(1024/128, NT/128), 256, HG_SMEM>>>(
        p_xh, p_xl, p_WBTh, p_WBTl, p_bB, p_Bmat, NT, 1024, DD);
    c_kernel<<<NT / 8, 256>>>(x);
    scan_kernel<<<BB, 32 * (NPROD + 1), SCAN_SMEM>>>(x);

    // join: site needed for M recovery, then final GEMM
    cudaStreamWaitEvent(0, evS, 0);
    mrec_kernel<<<NT, 128>>>();
    hgemm2_kernel<<<dim3(DD/128, NT/128), 256, HG_SMEM>>>(
        p_mh, p_ml, p_WcoTh, p_WcoTl, p_bco, p_y, NT, DD, 128);

    // join: gate needed for the epilogue
    cudaStreamWaitEvent(0, evG, 0);
    post_kernel<<<NT, 256>>>(x, gamma, beta, out);
}

// round 14
// speedup vs baseline: 1.4454x; 1.1620x over previous
#include <cuda_runtime.h>
#include <cuda_bf16.h>
#include <math.h>
#include <stdint.h>

// Problem dims
#define BB   4
#define LL   1024
#define DD   512
#define CHI  32
#define SS   4
#define NT   (BB*LL)          // 4096 tokens
#define CSC  (CHI*SS*CHI)     // 4096

// ---------------- scratch (__device__ globals, no allocs) ----------------
__device__ float g_site[(size_t)NT * CSC];       // x @ W_site + b_site     (64 MB)
__device__ float g_gate[(size_t)NT * DD];        // x @ W_gate + b_gate
__device__ float g_Bmat[(size_t)NT * CHI * CHI]; // B_t stored [t][r*32+l]
__device__ float g_WB[512 * 1024];               // pre-reduced site weights (fp32)
__device__ float g_bB[1024];                     // pre-reduced site bias
__device__ float g_c[(size_t)NT * CHI];          // c_t[r] = u_t @ B_t
__device__ float g_left[(size_t)NT * CHI];       // recorded left vectors
__device__ float g_y[(size_t)NT * DD];           // pre-LN y
__device__ float g_Wco[128 * 512];               // W_bridge @ W_out (fp32)
__device__ float g_bco[512];                     // b_bridge @ W_out + b_out

// pre-converted bf16 split operands
__device__ __nv_bfloat16 g_xh[(size_t)NT * DD],   g_xl[(size_t)NT * DD];
__device__ __nv_bfloat16 g_WsT_h[(size_t)CSC * DD], g_WsT_l[(size_t)CSC * DD];   // [n][k]
__device__ __nv_bfloat16 g_WgT_h[DD * DD],        g_WgT_l[DD * DD];
__device__ __nv_bfloat16 g_WBT_h[1024 * DD],      g_WBT_l[1024 * DD];
__device__ __nv_bfloat16 g_WcoT_h[DD * 128],      g_WcoT_l[DD * 128];
__device__ __nv_bfloat16 g_mh[(size_t)NT * 128],  g_ml[(size_t)NT * 128];

// ---------------- helpers ----------------
__device__ __forceinline__ uint32_t smem_u32(const void* p) {
    uint32_t a;
    asm("{ .reg .u64 t; cvta.to.shared.u64 t, %1; cvt.u32.u64 %0, t; }" : "=r"(a) : "l"(p));
    return a;
}
__device__ __forceinline__ void bsplit(float v, __nv_bfloat16& h, __nv_bfloat16& l)
{
    h = __float2bfloat16(v);
    l = __float2bfloat16(v - __bfloat162float(h));
}
#define CPA16(dst, src)  asm volatile("cp.async.cg.shared.global [%0], [%1], 16;" :: "r"(dst), "l"(src))
#define CPA_COMMIT()     asm volatile("cp.async.commit_group;" ::: "memory")
#define CPA_WAIT0()      asm volatile("cp.async.wait_group 0;" ::: "memory")
#define CPA_WAIT1()      asm volatile("cp.async.wait_group 1;" ::: "memory")

#define MMA_BF16(d, a0, a1, a2, a3, b0, b1)                                   \
    asm volatile("mma.sync.aligned.m16n8k16.row.col.f32.bf16.bf16.f32 "       \
                 "{%0,%1,%2,%3}, {%4,%5,%6,%7}, {%8,%9}, {%0,%1,%2,%3};\n"    \
                 : "+f"(d[0]), "+f"(d[1]), "+f"(d[2]), "+f"(d[3])             \
                 : "r"(a0), "r"(a1), "r"(a2), "r"(a3), "r"(b0), "r"(b1))

#define LDSM4(r, addr)                                                        \
    asm volatile("ldmatrix.sync.aligned.m8n8.x4.shared.b16 {%0,%1,%2,%3}, [%4];" \
                 : "=r"((r)[0]), "=r"((r)[1]), "=r"((r)[2]), "=r"((r)[3])     \
                 : "r"(addr))

// ---------------- x -> bf16 split ----------------
__global__ void xcvt_kernel(const float* __restrict__ x)
{
    int i = blockIdx.x * 256 + threadIdx.x;      // NT*DD = 2M
    __nv_bfloat16 h, l;
    bsplit(x[i], h, l);
    g_xh[i] = h; g_xl[i] = l;
}

// ---------------- transpose + split: src[K][N] fp32 -> dh/dl[N][K] bf16 ----
__global__ void tsplit_kernel(const float* __restrict__ src,
                              __nv_bfloat16* __restrict__ dh,
                              __nv_bfloat16* __restrict__ dl, int K, int N)
{
    __shared__ float t[32][33];
    int bn = blockIdx.x * 32, bk = blockIdx.y * 32;
    int tx = threadIdx.x, ty = threadIdx.y;
#pragma unroll
    for (int i = ty; i < 32; i += 8)
        t[i][tx] = src[(size_t)(bk + i) * N + bn + tx];
    __syncthreads();
#pragma unroll
    for (int i = ty; i < 32; i += 8) {
        __nv_bfloat16 h, l;
        bsplit(t[tx][i], h, l);                  // = src[bk+tx][bn+i]
        dh[(size_t)(bn + i) * K + bk + tx] = h;
        dl[(size_t)(bn + i) * K + bk + tx] = l;
    }
}

// ---------------- prep: fuse bridge+out weights (fp32) ----------------
__global__ void prep_kernel(const float* __restrict__ Wb, const float* __restrict__ bb,
                            const float* __restrict__ Wo, const float* __restrict__ bo)
{
    int idx = blockIdx.x * blockDim.x + threadIdx.x;   // 0..65535
    int pr = idx >> 9, j = idx & 511;
    float s = 0.f;
#pragma unroll
    for (int i = 0; i < 32; ++i)
        s = fmaf(Wb[pr * 32 + i], Wo[i * 512 + j], s);
    g_Wco[idx] = s;
    if (idx < 512) {
        float c = bo[idx];
#pragma unroll
        for (int i = 0; i < 32; ++i)
            c = fmaf(bb[i], Wo[i * 512 + idx], c);
        g_bco[idx] = c;
    }
}

// ---------------- reduce W_site over physical index -> W_B (fp32) ----------
__global__ __launch_bounds__(256) void wb_kernel(const float* __restrict__ Ws,
                                                 const float* __restrict__ bs)
{
    int idx = blockIdx.x * 256 + threadIdx.x;          // 0 .. 512*1024-1
    int d = idx >> 10, rem = idx & 1023;
    int l = rem >> 5, r = rem & 31;
    const float* p = Ws + (size_t)d * 4096 + l * 128 + r;   // coalesced in r
    g_WB[(size_t)d * 1024 + r * 32 + l] = p[0] + p[32] + p[64] + p[96];
    if (idx < 1024) {
        int ll = idx >> 5, rr = idx & 31;
        const float* q = bs + ll * 128 + rr;
        g_bB[rr * 32 + ll] = q[0] + q[32] + q[64] + q[96];
    }
}

// ============ bf16-split tensor GEMM: C = A[MxK] @ B[KxN] + bias ===========
#define HG_SMEM (2 * 40960)

__device__ __forceinline__ void hg_load(uint32_t sb,
    const __nv_bfloat16* __restrict__ Ah, const __nv_bfloat16* __restrict__ Al,
    const __nv_bfloat16* __restrict__ Bh, const __nv_bfloat16* __restrict__ Bl,
    int bm, int bn, int K, int k0, int tid)
{
#pragma unroll
    for (int q = 0; q < 2; ++q) {
        int id = tid + 256 * q;                  // 0..511
        int r = id >> 2, c = id & 3;
        uint32_t so = (uint32_t)(r * 80 + c * 16);
        size_t goA = (size_t)(bm + r) * K + k0 + c * 8;
        size_t goB = (size_t)(bn + r) * K + k0 + c * 8;
        CPA16(sb + so,          Ah + goA);
        CPA16(sb + 10240 + so,  Al + goA);
        CPA16(sb + 20480 + so,  Bh + goB);
        CPA16(sb + 30720 + so,  Bl + goB);
    }
}

__device__ __forceinline__ void hg_compute(uint32_t sb, float acc[4][4][4],
                                           int m0w, int n0w, int lane)
{
    const int arow = (lane & 15);
    const int acolb = (lane >> 4) * 16;
    const int brow = (lane & 7) + ((lane >> 4) << 3);
    const int bcolb = ((lane >> 3) & 1) * 16;
#pragma unroll
    for (int kk = 0; kk < 2; ++kk) {
        const int kb = kk * 32;                  // 16 bf16 = 32 bytes
        uint32_t ah[4][4], al[4][4], bh[2][4], bl[2][4];
#pragma unroll
        for (int mi = 0; mi < 4; ++mi) {
            uint32_t adr = sb + (uint32_t)((m0w + mi * 16 + arow) * 80 + kb + acolb);
            LDSM4(ah[mi], adr);
            LDSM4(al[mi], adr + 10240);
        }
#pragma unroll
        for (int np = 0; np < 2; ++np) {
            uint32_t adr = sb + 20480 + (uint32_t)((n0w + np * 16 + brow) * 80 + kb + bcolb);
            LDSM4(bh[np], adr);
            LDSM4(bl[np], adr + 10240);
        }
#pragma unroll
        for (int ni = 0; ni < 4; ++ni) {
            uint32_t h0 = bh[ni >> 1][(ni & 1) * 2], h1 = bh[ni >> 1][(ni & 1) * 2 + 1];
            uint32_t l0 = bl[ni >> 1][(ni & 1) * 2], l1 = bl[ni >> 1][(ni & 1) * 2 + 1];
#pragma unroll
            for (int mi = 0; mi < 4; ++mi) {
                MMA_BF16(acc[mi][ni], ah[mi][0], ah[mi][1], ah[mi][2], ah[mi][3], h0, h1);
                MMA_BF16(acc[mi][ni], ah[mi][0], ah[mi][1], ah[mi][2], ah[mi][3], l0, l1);
                MMA_BF16(acc[mi][ni], al[mi][0], al[mi][1], al[mi][2], al[mi][3], h0, h1);
            }
        }
    }
}

__global__ __launch_bounds__(256, 1)
void hgemm2_kernel(const __nv_bfloat16* __restrict__ Ah, const __nv_bfloat16* __restrict__ Al,
                   const __nv_bfloat16* __restrict__ Bh, const __nv_bfloat16* __restrict__ Bl,
                   const float* __restrict__ bias, float* __restrict__ C,
                   int M, int N, int K)
{
    extern __shared__ __align__(16) char smem[];
    const int tid = threadIdx.x;
    const int warp = tid >> 5, lane = tid & 31;
    const int g = lane >> 2, tg = lane & 3;
    const int m0w = (warp >> 2) * 64;            // 0 | 64
    const int n0w = (warp & 3) * 32;             // 0..96
    const int bm = blockIdx.y * 128, bn = blockIdx.x * 128;
    const uint32_t sb = smem_u32(smem);

    float acc[4][4][4];
#pragma unroll
    for (int i = 0; i < 4; ++i)
#pragma unroll
        for (int j = 0; j < 4; ++j)
#pragma unroll
            for (int e = 0; e < 4; ++e) acc[i][j][e] = 0.f;

    const int nk = K >> 5;
    hg_load(sb, Ah, Al, Bh, Bl, bm, bn, K, 0, tid);
    CPA_COMMIT();
    for (int i = 0; i < nk; ++i) {
        if (i + 1 < nk) {
            hg_load(sb + ((i + 1) & 1) * 40960, Ah, Al, Bh, Bl, bm, bn, K, (i + 1) * 32, tid);
            CPA_COMMIT();
            CPA_WAIT1();
        } else {
            CPA_WAIT0();
        }
        __syncthreads();
        hg_compute(sb + (uint32_t)((i & 1) * 40960), acc, m0w, n0w, lane);
        __syncthreads();
    }

#pragma unroll
    for (int mi = 0; mi < 4; ++mi) {
        int row = bm + m0w + mi * 16 + g;
#pragma unroll
        for (int ni = 0; ni < 4; ++ni) {
            int col = bn + n0w + ni * 8 + 2 * tg;
            float b0 = bias[col], b1 = bias[col + 1];
            *(float2*)&C[(size_t)row * N + col] =
                make_float2(acc[mi][ni][0] + b0, acc[mi][ni][1] + b1);
            *(float2*)&C[(size_t)(row + 8) * N + col] =
                make_float2(acc[mi][ni][2] + b0, acc[mi][ni][3] + b1);
        }
    }
}

// ---------------- c_t[r] = sum_l u_t[l] * B_t[l][r] (8 tokens/block) -------
__global__ __launch_bounds__(256) void c_kernel(const float* __restrict__ x)
{
    int t = blockIdx.x * 8 + (threadIdx.x >> 5);
    int r = threadIdx.x & 31;
    float u = x[(size_t)t * DD + r];           // lane l holds u_l
    const float* brow = g_Bmat + (size_t)t * 1024 + r * 32;
    float4 b4[8];
#pragma unroll
    for (int q = 0; q < 8; ++q) b4[q] = __ldg((const float4*)(brow + 4 * q));
    float c = 0.f;
#pragma unroll
    for (int q = 0; q < 8; ++q) {
        c = fmaf(__shfl_sync(0xffffffffu, u, 4 * q + 0), b4[q].x, c);
        c = fmaf(__shfl_sync(0xffffffffu, u, 4 * q + 1), b4[q].y, c);
        c = fmaf(__shfl_sync(0xffffffffu, u, 4 * q + 2), b4[q].z, c);
        c = fmaf(__shfl_sync(0xffffffffu, u, 4 * q + 3), b4[q].w, c);
    }
    g_c[(size_t)t * 32 + r] = c;
}

// ========== sequential scan: producer/consumer smem ring ==========
// Block = 288 threads (9 warps): warps 0-7 = cp.async producers (depth-2
// pipelined); warp 8 = serial consumer (highest wid wins arbitration).
// Producers spin with nanosleep to keep LSU/issue pressure off the consumer.
#define NS    24
#define STGB  4864                      // 32*144 + 128 (c) + 128 (u)
#define SCAN_SMEM (NS * STGB)
#define NPROD 8

__device__ __forceinline__ float scan_step(float v, const float4* BC, float cc,
                                           float uu, float* leftp)
{
    // 8 independent w-chains + 8 s-chains (depth 4) off the same broadcasts
    float w[8], s[8];
#pragma unroll
    for (int q = 0; q < 8; ++q) {
        float va = __shfl_sync(0xffffffffu, v, 4*q + 0);
        float vb = __shfl_sync(0xffffffffu, v, 4*q + 1);
        float vc = __shfl_sync(0xffffffffu, v, 4*q + 2);
        float vd = __shfl_sync(0xffffffffu, v, 4*q + 3);
        float wq, sq;
        wq = va * BC[q].x;          sq = va * va;
        wq = fmaf(vb, BC[q].y, wq); sq = fmaf(vb, vb, sq);
        wq = fmaf(vc, BC[q].z, wq); sq = fmaf(vc, vc, sq);
        wq = fmaf(vd, BC[q].w, wq); sq = fmaf(vd, vd, sq);
        w[q] = wq; s[q] = sq;
    }
    float wt = ((w[0] + w[1]) + (w[2] + w[3])) + ((w[4] + w[5]) + (w[6] + w[7]));
    float st = ((s[0] + s[1]) + (s[2] + s[3])) + ((s[4] + s[5]) + (s[6] + s[7]));
    float alpha = rsqrtf(st + 1e-24f);          // s==0 -> alpha*v == 0 == h0
    *leftp = fmaf(alpha, v, uu);
    return fmaf(alpha, wt, cc);
}

__device__ __forceinline__ void prod_issue(uint32_t base, size_t tg0, int s,
                                           int lane, const float* __restrict__ x)
{
    const char* gB = (const char*)(g_Bmat + (tg0 + s) * 1024);
#pragma unroll
    for (int q = 0; q < 8; ++q) {
        int i = lane + 32 * q;                       // 0..255 float4 chunks
        CPA16(base + (uint32_t)((i >> 3) * 144 + (i & 7) * 16), gB + i * 16);
    }
    if (lane < 8) {
        CPA16(base + 4608u + lane * 16,
              (const char*)(g_c + (tg0 + s) * 32) + lane * 16);
    } else if (lane < 16) {
        CPA16(base + 4736u + (lane - 8) * 16,
              (const char*)(x + (tg0 + s) * DD) + (lane - 8) * 16);
    }
}

__global__ __launch_bounds__(32 * (NPROD + 1), 1) void scan_kernel(const float* __restrict__ x)
{
    extern __shared__ __align__(16) char ring[];
    __shared__ volatile int flags[NS];
    __shared__ volatile int progress;

    const int b = blockIdx.x, tid = threadIdx.x;
    const int wid = tid >> 5, lane = tid & 31;
    const size_t tg0 = (size_t)b * LL;

    for (int i = tid; i < NS; i += 32 * (NPROD + 1)) flags[i] = 0;
    if (tid == 0) progress = 0;
    __syncthreads();

    if (wid < NPROD) {
        // ---- producers: warp w handles steps s ≡ w (mod NPROD), depth-2 ----
        const int w = wid;
        uint32_t rbase = smem_u32(ring);
        int s = w;
        prod_issue(rbase + (uint32_t)(s % NS) * STGB, tg0, s, lane, x);
        CPA_COMMIT();
        for (int next = s + NPROD; next < LL; next += NPROD) {
            if (next >= NS) {
                while (progress < next - NS + 1) { __nanosleep(64); }
            }
            prod_issue(rbase + (uint32_t)(next % NS) * STGB, tg0, next, lane, x);
            CPA_COMMIT();
            CPA_WAIT1();                      // oldest group (step s) done
            __threadfence_block();
            __syncwarp();
            if (lane == 0) flags[s % NS] = s + 1;
            s = next;
        }
        CPA_WAIT0();
        __threadfence_block();
        __syncwarp();
        if (lane == 0) flags[s % NS] = s + 1;
    } else {
        // ---- consumer (highest wid): the serial recurrence ----
        float v = 0.f;
        float* lp = g_left + tg0 * 32 + lane;
        int slot = 0;
        while (flags[0] < 1) {}
#pragma unroll 1
        for (int t = 0; t < LL; ++t) {
            const char* stg = ring + (size_t)slot * STGB;
            const float4* br = (const float4*)(stg + lane * 144);
            float4 B[8];
#pragma unroll
            for (int q = 0; q < 8; ++q) B[q] = br[q];
            float cc = *(const float*)(stg + 4608 + 4 * lane);
            float uu = *(const float*)(stg + 4736 + 4 * lane);
            int nslot = slot + 1; if (nslot == NS) nslot = 0;
            int nf = flags[nslot];            // early probe; hides under compute
            v = scan_step(v, B, cc, uu, lp);
            lp += 32;
            if (lane == 0) progress = t + 1;  // lockstep warp, no syncwarp needed
            if (t + 1 < LL && nf < t + 2) {
                while (flags[nslot] < t + 2) {}
            }
            slot = nslot;
        }
    }
}

// ------- recover Mt per token; emit bf16 split for the final GEMM ----------
__global__ __launch_bounds__(128) void mrec_kernel()
{
    __shared__ float sleft[32];
    int t = blockIdx.x, tid = threadIdx.x;
    if (tid < 32) sleft[tid] = g_left[(size_t)t * 32 + tid];
    __syncthreads();
    const float* row = g_site + (size_t)t * CSC;
    float m = 0.f;
#pragma unroll
    for (int l = 0; l < 32; ++l)
        m = fmaf(sleft[l], __ldcs(row + l * 128 + tid), m);   // streaming, coalesced
    __nv_bfloat16 h, lo;
    bsplit(m, h, lo);
    g_mh[(size_t)t * 128 + tid] = h;
    g_ml[(size_t)t * 128 + tid] = lo;
}

// ---------------- LayerNorm + sigmoid-gated residual ----------------
__global__ __launch_bounds__(256) void post_kernel(const float* __restrict__ x,
                                                   const float* __restrict__ gamma,
                                                   const float* __restrict__ beta,
                                                   float* __restrict__ out)
{
    __shared__ float red[256];
    int t = blockIdx.x, tid = threadIdx.x;
    size_t base = (size_t)t * DD;
    int j0 = tid, j1 = tid + 256;
    float y0 = g_y[base + j0], y1 = g_y[base + j1];

    red[tid] = y0 + y1;
    __syncthreads();
    for (int st = 128; st > 0; st >>= 1) {
        if (tid < st) red[tid] += red[tid + st];
        __syncthreads();
    }
    float mu = red[0] * (1.f / 512.f);
    __syncthreads();

    float d0 = y0 - mu, d1 = y1 - mu;
    red[tid] = d0 * d0 + d1 * d1;
    __syncthreads();
    for (int st = 128; st > 0; st >>= 1) {
        if (tid < st) red[tid] += red[tid + st];
        __syncthreads();
    }
    float var = red[0] * (1.f / 512.f);
    float rstd = rsqrtf(var + 1e-6f);

    float yn0 = d0 * rstd * gamma[j0] + beta[j0];
    float yn1 = d1 * rstd * gamma[j1] + beta[j1];
    float gl0 = g_gate[base + j0], gl1 = g_gate[base + j1];
    float gt0 = 1.f / (1.f + expf(-gl0));
    float gt1 = 1.f / (1.f + expf(-gl1));
    float xv0 = x[base + j0], xv1 = x[base + j1];
    out[base + j0] = gt0 * yn0 + (1.f - gt0) * xv0;
    out[base + j1] = gt1 * yn1 + (1.f - gt1) * xv1;
}

// ---------------- launch ----------------
extern "C" void kernel_launch(void* const* d_in, const int* in_sizes, int n_in,
                              void* d_out, int out_size)
{
    (void)in_sizes; (void)n_in; (void)out_size;
    const float* x       = (const float*)d_in[0];
    const float* W_site  = (const float*)d_in[1];
    const float* b_site  = (const float*)d_in[2];
    const float* W_bridge= (const float*)d_in[3];
    const float* b_bridge= (const float*)d_in[4];
    const float* W_out   = (const float*)d_in[5];
    const float* b_out   = (const float*)d_in[6];
    const float* gamma   = (const float*)d_in[7];
    const float* beta    = (const float*)d_in[8];
    const float* W_gate  = (const float*)d_in[9];
    const float* b_gate  = (const float*)d_in[10];
    float* out = (float*)d_out;

    static float *p_site, *p_gate, *p_y, *p_WB, *p_bB, *p_Wco, *p_bco, *p_Bmat;
    static __nv_bfloat16 *p_xh, *p_xl, *p_WsTh, *p_WsTl, *p_WgTh, *p_WgTl,
                         *p_WBTh, *p_WBTl, *p_WcoTh, *p_WcoTl, *p_mh, *p_ml;
    static cudaStream_t s1;
    static cudaEvent_t ev0, evB, evS, evG;
    static bool inited = false;
    if (!inited) {
        cudaGetSymbolAddress((void**)&p_site,  g_site);
        cudaGetSymbolAddress((void**)&p_gate,  g_gate);
        cudaGetSymbolAddress((void**)&p_y,     g_y);
        cudaGetSymbolAddress((void**)&p_WB,    g_WB);
        cudaGetSymbolAddress((void**)&p_bB,    g_bB);
        cudaGetSymbolAddress((void**)&p_Wco,   g_Wco);
        cudaGetSymbolAddress((void**)&p_bco,   g_bco);
        cudaGetSymbolAddress((void**)&p_Bmat,  g_Bmat);
        cudaGetSymbolAddress((void**)&p_xh,    g_xh);
        cudaGetSymbolAddress((void**)&p_xl,    g_xl);
        cudaGetSymbolAddress((void**)&p_WsTh,  g_WsT_h);
        cudaGetSymbolAddress((void**)&p_WsTl,  g_WsT_l);
        cudaGetSymbolAddress((void**)&p_WgTh,  g_WgT_h);
        cudaGetSymbolAddress((void**)&p_WgTl,  g_WgT_l);
        cudaGetSymbolAddress((void**)&p_WBTh,  g_WBT_h);
        cudaGetSymbolAddress((void**)&p_WBTl,  g_WBT_l);
        cudaGetSymbolAddress((void**)&p_WcoTh, g_WcoT_h);
        cudaGetSymbolAddress((void**)&p_WcoTl, g_WcoT_l);
        cudaGetSymbolAddress((void**)&p_mh,    g_mh);
        cudaGetSymbolAddress((void**)&p_ml,    g_ml);
        cudaStreamCreateWithFlags(&s1, cudaStreamNonBlocking);
        cudaEventCreateWithFlags(&ev0, cudaEventDisableTiming);
        cudaEventCreateWithFlags(&evB, cudaEventDisableTiming);
        cudaEventCreateWithFlags(&evS, cudaEventDisableTiming);
        cudaEventCreateWithFlags(&evG, cudaEventDisableTiming);
        cudaFuncSetAttribute(hgemm2_kernel, cudaFuncAttributeMaxDynamicSharedMemorySize, HG_SMEM);
        cudaFuncSetAttribute(scan_kernel, cudaFuncAttributeMaxDynamicSharedMemorySize, SCAN_SMEM);
        inited = true;
    }

    // shared prologue: x split (both branches need it)
    xcvt_kernel<<<(NT * DD) / 256, 256>>>(x);
    cudaEventRecord(ev0, 0);
    cudaStreamWaitEvent(s1, ev0, 0);

    // ---- main stream: scan-prerequisite chain gets the chip FIRST ----
    wb_kernel<<<2048, 256>>>(W_site, b_site);
    tsplit_kernel<<<dim3(32, 16), dim3(32, 8)>>>(p_WB, p_WBTh, p_WBTl, 512, 1024);
    hgemm2_kernel<<<dim3(1024/128, NT/128), 256, HG_SMEM>>>(
        p_xh, p_xl, p_WBTh, p_WBTl, p_bB, p_Bmat, NT, 1024, DD);
    cudaEventRecord(evB, 0);
    c_kernel<<<NT / 8, 256>>>(x);
    scan_kernel<<<BB, 32 * (NPROD + 1), SCAN_SMEM>>>(x);

    // ---- side stream: cheap prep concurrent; heavy GEMMs AFTER evB ----
    tsplit_kernel<<<dim3(128,16), dim3(32, 8), 0, s1>>>(W_site, p_WsTh, p_WsTl, 512, 4096);
    prep_kernel<<<256, 256, 0, s1>>>(W_bridge, b_bridge, W_out, b_out);
    tsplit_kernel<<<dim3(16, 4),  dim3(32, 8), 0, s1>>>(p_Wco,  p_WcoTh, p_WcoTl, 128, 512);
    tsplit_kernel<<<dim3(16, 16), dim3(32, 8), 0, s1>>>(W_gate, p_WgTh,  p_WgTl,  512, 512);
    cudaStreamWaitEvent(s1, evB, 0);
    hgemm2_kernel<<<dim3(CSC/128, NT/128), 256, HG_SMEM, s1>>>(
        p_xh, p_xl, p_WsTh, p_WsTl, b_site, p_site, NT, CSC, DD);
    cudaEventRecord(evS, s1);
    hgemm2_kernel<<<dim3(DD/128, NT/128), 256, HG_SMEM, s1>>>(
        p_xh, p_xl, p_WgTh, p_WgTl, b_gate, p_gate, NT, DD, DD);
    cudaEventRecord(evG, s1);

    // join: g_left (scan, main-stream order) + site (evS) -> mrec -> final GEMM
    cudaStreamWaitEvent(0, evS, 0);
    mrec_kernel<<<NT, 128>>>();
    hgemm2_kernel<<<dim3(DD/128, NT/128), 256, HG_SMEM>>>(
        p_mh, p_ml, p_WcoTh, p_WcoTl, p_bco, p_y, NT, DD, 128);

    // join: gate needed for the epilogue
    cudaStreamWaitEvent(0, evG, 0);
    post_kernel<<<NT, 256>>>(x, gamma, beta, out);
}

// round 15
// speedup vs baseline: 1.4519x; 1.0045x over previous
#include <cuda_runtime.h>
#include <cuda_bf16.h>
#include <math.h>
#include <stdint.h>

// Problem dims
#define BB   4
#define LL   1024
#define DD   512
#define CHI  32
#define SS   4
#define NT   (BB*LL)          // 4096 tokens
#define CSC  (CHI*SS*CHI)     // 4096

// ---------------- scratch (__device__ globals, no allocs) ----------------
__device__ float g_site[(size_t)NT * CSC];       // x @ W_site + b_site     (64 MB)
__device__ float g_gate[(size_t)NT * DD];        // x @ W_gate + b_gate
__device__ float g_Bmat[(size_t)NT * CHI * CHI]; // B_t stored [t][r*32+l]
__device__ float g_WB[512 * 1024];               // pre-reduced site weights (fp32)
__device__ float g_bB[1024];                     // pre-reduced site bias
__device__ float g_c[(size_t)NT * CHI];          // c_t[r] = u_t @ B_t
__device__ float g_left[(size_t)NT * CHI];       // recorded left vectors
__device__ float g_y[(size_t)NT * DD];           // pre-LN y
__device__ float g_Wco[128 * 512];               // W_bridge @ W_out (fp32)
__device__ float g_bco[512];                     // b_bridge @ W_out + b_out

// pre-converted bf16 split operands
__device__ __nv_bfloat16 g_xh[(size_t)NT * DD],   g_xl[(size_t)NT * DD];
__device__ __nv_bfloat16 g_WsT_h[(size_t)CSC * DD], g_WsT_l[(size_t)CSC * DD];   // [n][k]
__device__ __nv_bfloat16 g_WgT_h[DD * DD],        g_WgT_l[DD * DD];
__device__ __nv_bfloat16 g_WBT_h[1024 * DD],      g_WBT_l[1024 * DD];
__device__ __nv_bfloat16 g_WcoT_h[DD * 128],      g_WcoT_l[DD * 128];
__device__ __nv_bfloat16 g_mh[(size_t)NT * 128],  g_ml[(size_t)NT * 128];

// ---------------- helpers ----------------
__device__ __forceinline__ uint32_t smem_u32(const void* p) {
    uint32_t a;
    asm("{ .reg .u64 t; cvta.to.shared.u64 t, %1; cvt.u32.u64 %0, t; }" : "=r"(a) : "l"(p));
    return a;
}
__device__ __forceinline__ void bsplit(float v, __nv_bfloat16& h, __nv_bfloat16& l)
{
    h = __float2bfloat16(v);
    l = __float2bfloat16(v - __bfloat162float(h));
}
__device__ __forceinline__ uint32_t pkbf2(__nv_bfloat16 a, __nv_bfloat16 b)
{
    __nv_bfloat162 t; t.x = a; t.y = b;
    uint32_t u; *(__nv_bfloat162*)&u = t; return u;
}
#define CPA16(dst, src)  asm volatile("cp.async.cg.shared.global [%0], [%1], 16;" :: "r"(dst), "l"(src))
#define CPA_COMMIT()     asm volatile("cp.async.commit_group;" ::: "memory")
#define CPA_WAIT0()      asm volatile("cp.async.wait_group 0;" ::: "memory")
#define CPA_WAIT1()      asm volatile("cp.async.wait_group 1;" ::: "memory")

#define MMA_BF16(d, a0, a1, a2, a3, b0, b1)                                   \
    asm volatile("mma.sync.aligned.m16n8k16.row.col.f32.bf16.bf16.f32 "       \
                 "{%0,%1,%2,%3}, {%4,%5,%6,%7}, {%8,%9}, {%0,%1,%2,%3};\n"    \
                 : "+f"(d[0]), "+f"(d[1]), "+f"(d[2]), "+f"(d[3])             \
                 : "r"(a0), "r"(a1), "r"(a2), "r"(a3), "r"(b0), "r"(b1))

#define LDSM4(r, addr)                                                        \
    asm volatile("ldmatrix.sync.aligned.m8n8.x4.shared.b16 {%0,%1,%2,%3}, [%4];" \
                 : "=r"((r)[0]), "=r"((r)[1]), "=r"((r)[2]), "=r"((r)[3])     \
                 : "r"(addr))

// ---------------- x -> bf16 split ----------------
__global__ void xcvt_kernel(const float* __restrict__ x)
{
    int i = blockIdx.x * 256 + threadIdx.x;      // NT*DD = 2M
    __nv_bfloat16 h, l;
    bsplit(x[i], h, l);
    g_xh[i] = h; g_xl[i] = l;
}

// ---------------- transpose + split: src[K][N] fp32 -> dh/dl[N][K] bf16 ----
__global__ void tsplit_kernel(const float* __restrict__ src,
                              __nv_bfloat16* __restrict__ dh,
                              __nv_bfloat16* __restrict__ dl, int K, int N)
{
    __shared__ float t[32][33];
    int bn = blockIdx.x * 32, bk = blockIdx.y * 32;
    int tx = threadIdx.x, ty = threadIdx.y;
#pragma unroll
    for (int i = ty; i < 32; i += 8)
        t[i][tx] = src[(size_t)(bk + i) * N + bn + tx];
    __syncthreads();
#pragma unroll
    for (int i = ty; i < 32; i += 8) {
        __nv_bfloat16 h, l;
        bsplit(t[tx][i], h, l);                  // = src[bk+tx][bn+i]
        dh[(size_t)(bn + i) * K + bk + tx] = h;
        dl[(size_t)(bn + i) * K + bk + tx] = l;
    }
}

// ---------------- prep: fuse bridge+out weights (fp32) ----------------
__global__ void prep_kernel(const float* __restrict__ Wb, const float* __restrict__ bb,
                            const float* __restrict__ Wo, const float* __restrict__ bo)
{
    int idx = blockIdx.x * blockDim.x + threadIdx.x;   // 0..65535
    int pr = idx >> 9, j = idx & 511;
    float s = 0.f;
#pragma unroll
    for (int i = 0; i < 32; ++i)
        s = fmaf(Wb[pr * 32 + i], Wo[i * 512 + j], s);
    g_Wco[idx] = s;
    if (idx < 512) {
        float c = bo[idx];
#pragma unroll
        for (int i = 0; i < 32; ++i)
            c = fmaf(bb[i], Wo[i * 512 + idx], c);
        g_bco[idx] = c;
    }
}

// ---------------- reduce W_site over physical index -> W_B (fp32) ----------
__global__ __launch_bounds__(256) void wb_kernel(const float* __restrict__ Ws,
                                                 const float* __restrict__ bs)
{
    int idx = blockIdx.x * 256 + threadIdx.x;          // 0 .. 512*1024-1
    int d = idx >> 10, rem = idx & 1023;
    int l = rem >> 5, r = rem & 31;
    const float* p = Ws + (size_t)d * 4096 + l * 128 + r;   // coalesced in r
    g_WB[(size_t)d * 1024 + r * 32 + l] = p[0] + p[32] + p[64] + p[96];
    if (idx < 1024) {
        int ll = idx >> 5, rr = idx & 31;
        const float* q = bs + ll * 128 + rr;
        g_bB[rr * 32 + ll] = q[0] + q[32] + q[64] + q[96];
    }
}

// ============ bf16-split tensor GEMM: C = A[MxK] @ B[KxN] + bias ===========
#define HG_SMEM (2 * 40960)

__device__ __forceinline__ void hg_load(uint32_t sb,
    const __nv_bfloat16* __restrict__ Ah, const __nv_bfloat16* __restrict__ Al,
    const __nv_bfloat16* __restrict__ Bh, const __nv_bfloat16* __restrict__ Bl,
    int bm, int bn, int K, int k0, int tid)
{
#pragma unroll
    for (int q = 0; q < 2; ++q) {
        int id = tid + 256 * q;                  // 0..511
        int r = id >> 2, c = id & 3;
        uint32_t so = (uint32_t)(r * 80 + c * 16);
        size_t goA = (size_t)(bm + r) * K + k0 + c * 8;
        size_t goB = (size_t)(bn + r) * K + k0 + c * 8;
        CPA16(sb + so,          Ah + goA);
        CPA16(sb + 10240 + so,  Al + goA);
        CPA16(sb + 20480 + so,  Bh + goB);
        CPA16(sb + 30720 + so,  Bl + goB);
    }
}

__device__ __forceinline__ void hg_compute(uint32_t sb, float acc[4][4][4],
                                           int m0w, int n0w, int lane)
{
    const int arow = (lane & 15);
    const int acolb = (lane >> 4) * 16;
    const int brow = (lane & 7) + ((lane >> 4) << 3);
    const int bcolb = ((lane >> 3) & 1) * 16;
#pragma unroll
    for (int kk = 0; kk < 2; ++kk) {
        const int kb = kk * 32;                  // 16 bf16 = 32 bytes
        uint32_t ah[4][4], al[4][4], bh[2][4], bl[2][4];
#pragma unroll
        for (int mi = 0; mi < 4; ++mi) {
            uint32_t adr = sb + (uint32_t)((m0w + mi * 16 + arow) * 80 + kb + acolb);
            LDSM4(ah[mi], adr);
            LDSM4(al[mi], adr + 10240);
        }
#pragma unroll
        for (int np = 0; np < 2; ++np) {
            uint32_t adr = sb + 20480 + (uint32_t)((n0w + np * 16 + brow) * 80 + kb + bcolb);
            LDSM4(bh[np], adr);
            LDSM4(bl[np], adr + 10240);
        }
#pragma unroll
        for (int ni = 0; ni < 4; ++ni) {
            uint32_t h0 = bh[ni >> 1][(ni & 1) * 2], h1 = bh[ni >> 1][(ni & 1) * 2 + 1];
            uint32_t l0 = bl[ni >> 1][(ni & 1) * 2], l1 = bl[ni >> 1][(ni & 1) * 2 + 1];
#pragma unroll
            for (int mi = 0; mi < 4; ++mi) {
                MMA_BF16(acc[mi][ni], ah[mi][0], ah[mi][1], ah[mi][2], ah[mi][3], h0, h1);
                MMA_BF16(acc[mi][ni], ah[mi][0], ah[mi][1], ah[mi][2], ah[mi][3], l0, l1);
                MMA_BF16(acc[mi][ni], al[mi][0], al[mi][1], al[mi][2], al[mi][3], h0, h1);
            }
        }
    }
}

__global__ __launch_bounds__(256, 1)
void hgemm2_kernel(const __nv_bfloat16* __restrict__ Ah, const __nv_bfloat16* __restrict__ Al,
                   const __nv_bfloat16* __restrict__ Bh, const __nv_bfloat16* __restrict__ Bl,
                   const float* __restrict__ bias, float* __restrict__ C,
                   int M, int N, int K)
{
    extern __shared__ __align__(16) char smem[];
    const int tid = threadIdx.x;
    const int warp = tid >> 5, lane = tid & 31;
    const int g = lane >> 2, tg = lane & 3;
    const int m0w = (warp >> 2) * 64;            // 0 | 64
    const int n0w = (warp & 3) * 32;             // 0..96
    const int bm = blockIdx.y * 128, bn = blockIdx.x * 128;
    const uint32_t sb = smem_u32(smem);

    float acc[4][4][4];
#pragma unroll
    for (int i = 0; i < 4; ++i)
#pragma unroll
        for (int j = 0; j < 4; ++j)
#pragma unroll
            for (int e = 0; e < 4; ++e) acc[i][j][e] = 0.f;

    const int nk = K >> 5;
    hg_load(sb, Ah, Al, Bh, Bl, bm, bn, K, 0, tid);
    CPA_COMMIT();
    for (int i = 0; i < nk; ++i) {
        if (i + 1 < nk) {
            hg_load(sb + ((i + 1) & 1) * 40960, Ah, Al, Bh, Bl, bm, bn, K, (i + 1) * 32, tid);
            CPA_COMMIT();
            CPA_WAIT1();
        } else {
            CPA_WAIT0();
        }
        __syncthreads();
        hg_compute(sb + (uint32_t)((i & 1) * 40960), acc, m0w, n0w, lane);
        __syncthreads();
    }

#pragma unroll
    for (int mi = 0; mi < 4; ++mi) {
        int row = bm + m0w + mi * 16 + g;
#pragma unroll
        for (int ni = 0; ni < 4; ++ni) {
            int col = bn + n0w + ni * 8 + 2 * tg;
            float b0 = bias[col], b1 = bias[col + 1];
            *(float2*)&C[(size_t)row * N + col] =
                make_float2(acc[mi][ni][0] + b0, acc[mi][ni][1] + b1);
            *(float2*)&C[(size_t)(row + 8) * N + col] =
                make_float2(acc[mi][ni][2] + b0, acc[mi][ni][3] + b1);
        }
    }
}

// ---------------- c_t[r] = sum_l u_t[l] * B_t[l][r] (8 tokens/block) -------
__global__ __launch_bounds__(256) void c_kernel(const float* __restrict__ x)
{
    int t = blockIdx.x * 8 + (threadIdx.x >> 5);
    int r = threadIdx.x & 31;
    float u = x[(size_t)t * DD + r];           // lane l holds u_l
    const float* brow = g_Bmat + (size_t)t * 1024 + r * 32;
    float4 b4[8];
#pragma unroll
    for (int q = 0; q < 8; ++q) b4[q] = __ldg((const float4*)(brow + 4 * q));
    float c = 0.f;
#pragma unroll
    for (int q = 0; q < 8; ++q) {
        c = fmaf(__shfl_sync(0xffffffffu, u, 4 * q + 0), b4[q].x, c);
        c = fmaf(__shfl_sync(0xffffffffu, u, 4 * q + 1), b4[q].y, c);
        c = fmaf(__shfl_sync(0xffffffffu, u, 4 * q + 2), b4[q].z, c);
        c = fmaf(__shfl_sync(0xffffffffu, u, 4 * q + 3), b4[q].w, c);
    }
    g_c[(size_t)t * 32 + r] = c;
}

// ========== sequential scan: producer/consumer smem ring ==========
// Block = 288 threads (9 warps): warps 0-7 = cp.async producers (depth-2
// pipelined); warp 8 = serial consumer (highest wid wins arbitration).
// NS=32 -> 152 KB smem: no hgemm CTA (80 KB) can co-reside; the scan block
// owns its SM's issue slots exclusively.
#define NS    32
#define STGB  4864                      // 32*144 + 128 (c) + 128 (u)
#define SCAN_SMEM (NS * STGB)
#define NPROD 8

__device__ __forceinline__ float scan_step(float v, const float4* BC, float cc,
                                           float uu, float* leftp)
{
    // 8 independent w-chains + 8 s-chains (depth 4) off the same broadcasts
    float w[8], s[8];
#pragma unroll
    for (int q = 0; q < 8; ++q) {
        float va = __shfl_sync(0xffffffffu, v, 4*q + 0);
        float vb = __shfl_sync(0xffffffffu, v, 4*q + 1);
        float vc = __shfl_sync(0xffffffffu, v, 4*q + 2);
        float vd = __shfl_sync(0xffffffffu, v, 4*q + 3);
        float wq, sq;
        wq = va * BC[q].x;          sq = va * va;
        wq = fmaf(vb, BC[q].y, wq); sq = fmaf(vb, vb, sq);
        wq = fmaf(vc, BC[q].z, wq); sq = fmaf(vc, vc, sq);
        wq = fmaf(vd, BC[q].w, wq); sq = fmaf(vd, vd, sq);
        w[q] = wq; s[q] = sq;
    }
    float wt = ((w[0] + w[1]) + (w[2] + w[3])) + ((w[4] + w[5]) + (w[6] + w[7]));
    float st = ((s[0] + s[1]) + (s[2] + s[3])) + ((s[4] + s[5]) + (s[6] + s[7]));
    float alpha = rsqrtf(st + 1e-24f);          // s==0 -> alpha*v == 0 == h0
    *leftp = fmaf(alpha, v, uu);
    return fmaf(alpha, wt, cc);
}

__device__ __forceinline__ void prod_issue(uint32_t base, size_t tg0, int s,
                                           int lane, const float* __restrict__ x)
{
    const char* gB = (const char*)(g_Bmat + (tg0 + s) * 1024);
#pragma unroll
    for (int q = 0; q < 8; ++q) {
        int i = lane + 32 * q;                       // 0..255 float4 chunks
        CPA16(base + (uint32_t)((i >> 3) * 144 + (i & 7) * 16), gB + i * 16);
    }
    if (lane < 8) {
        CPA16(base + 4608u + lane * 16,
              (const char*)(g_c + (tg0 + s) * 32) + lane * 16);
    } else if (lane < 16) {
        CPA16(base + 4736u + (lane - 8) * 16,
              (const char*)(x + (tg0 + s) * DD) + (lane - 8) * 16);
    }
}

__global__ __launch_bounds__(32 * (NPROD + 1), 1) void scan_kernel(const float* __restrict__ x)
{
    extern __shared__ __align__(16) char ring[];
    __shared__ volatile int flags[NS];
    __shared__ volatile int progress;

    const int b = blockIdx.x, tid = threadIdx.x;
    const int wid = tid >> 5, lane = tid & 31;
    const size_t tg0 = (size_t)b * LL;

    for (int i = tid; i < NS; i += 32 * (NPROD + 1)) flags[i] = 0;
    if (tid == 0) progress = 0;
    __syncthreads();

    if (wid < NPROD) {
        // ---- producers: warp w handles steps s ≡ w (mod NPROD), depth-2 ----
        const int w = wid;
        uint32_t rbase = smem_u32(ring);
        int s = w;
        prod_issue(rbase + (uint32_t)(s % NS) * STGB, tg0, s, lane, x);
        CPA_COMMIT();
        for (int next = s + NPROD; next < LL; next += NPROD) {
            if (next >= NS) {
                while (progress < next - NS + 1) { __nanosleep(64); }
            }
            prod_issue(rbase + (uint32_t)(next % NS) * STGB, tg0, next, lane, x);
            CPA_COMMIT();
            CPA_WAIT1();                      // oldest group (step s) done
            __threadfence_block();
            __syncwarp();
            if (lane == 0) flags[s % NS] = s + 1;
            s = next;
        }
        CPA_WAIT0();
        __threadfence_block();
        __syncwarp();
        if (lane == 0) flags[s % NS] = s + 1;
    } else {
        // ---- consumer (highest wid): the serial recurrence ----
        float v = 0.f;
        float* lp = g_left + tg0 * 32 + lane;
        int slot = 0;
        while (flags[0] < 1) {}
#pragma unroll 1
        for (int t = 0; t < LL; ++t) {
            const char* stg = ring + (size_t)slot * STGB;
            const float4* br = (const float4*)(stg + lane * 144);
            float4 B[8];
#pragma unroll
            for (int q = 0; q < 8; ++q) B[q] = br[q];
            float cc = *(const float*)(stg + 4608 + 4 * lane);
            float uu = *(const float*)(stg + 4736 + 4 * lane);
            int nslot = slot + 1; if (nslot == NS) nslot = 0;
            int nf = flags[nslot];            // early probe; hides under compute
            v = scan_step(v, B, cc, uu, lp);
            lp += 32;
            if (lane == 0) progress = t + 1;  // lockstep warp, no syncwarp needed
            if (t + 1 < LL && nf < t + 2) {
                while (flags[nslot] < t + 2) {}
            }
            slot = nslot;
        }
    }
}

// ------- recover Mt per token; emit bf16 split for the final GEMM ----------
// Warp-per-token, float4 streaming loads; 8 tokens per 256-thread block.
__global__ __launch_bounds__(256) void mrec_kernel()
{
    int t = blockIdx.x * 8 + (threadIdx.x >> 5);
    int lane = threadIdx.x & 31;
    float lf = g_left[(size_t)t * 32 + lane];       // lane l holds left[l]
    const float* row = g_site + (size_t)t * CSC;

    float4 m = make_float4(0.f, 0.f, 0.f, 0.f);
#pragma unroll
    for (int l = 0; l < 32; ++l) {
        float s = __shfl_sync(0xffffffffu, lf, l);
        float4 rv = __ldcs((const float4*)(row + l * 128 + 4 * lane));
        m.x = fmaf(s, rv.x, m.x);
        m.y = fmaf(s, rv.y, m.y);
        m.z = fmaf(s, rv.z, m.z);
        m.w = fmaf(s, rv.w, m.w);
    }
    __nv_bfloat16 hx, lx, hy, ly, hz, lz, hw, lw;
    bsplit(m.x, hx, lx); bsplit(m.y, hy, ly);
    bsplit(m.z, hz, lz); bsplit(m.w, hw, lw);
    size_t o = (size_t)t * 128 + 4 * lane;
    uint2 ph = make_uint2(pkbf2(hx, hy), pkbf2(hz, hw));
    uint2 pl = make_uint2(pkbf2(lx, ly), pkbf2(lz, lw));
    *(uint2*)(g_mh + o) = ph;
    *(uint2*)(g_ml + o) = pl;
}

// ---------------- LayerNorm + sigmoid-gated residual ----------------
__global__ __launch_bounds__(256) void post_kernel(const float* __restrict__ x,
                                                   const float* __restrict__ gamma,
                                                   const float* __restrict__ beta,
                                                   float* __restrict__ out)
{
    __shared__ float red[256];
    int t = blockIdx.x, tid = threadIdx.x;
    size_t base = (size_t)t * DD;
    int j0 = tid, j1 = tid + 256;
    float y0 = g_y[base + j0], y1 = g_y[base + j1];

    red[tid] = y0 + y1;
    __syncthreads();
    for (int st = 128; st > 0; st >>= 1) {
        if (tid < st) red[tid] += red[tid + st];
        __syncthreads();
    }
    float mu = red[0] * (1.f / 512.f);
    __syncthreads();

    float d0 = y0 - mu, d1 = y1 - mu;
    red[tid] = d0 * d0 + d1 * d1;
    __syncthreads();
    for (int st = 128; st > 0; st >>= 1) {
        if (tid < st) red[tid] += red[tid + st];
        __syncthreads();
    }
    float var = red[0] * (1.f / 512.f);
    float rstd = rsqrtf(var + 1e-6f);

    float yn0 = d0 * rstd * gamma[j0] + beta[j0];
    float yn1 = d1 * rstd * gamma[j1] + beta[j1];
    float gl0 = g_gate[base + j0], gl1 = g_gate[base + j1];
    float gt0 = 1.f / (1.f + expf(-gl0));
    float gt1 = 1.f / (1.f + expf(-gl1));
    float xv0 = x[base + j0], xv1 = x[base + j1];
    out[base + j0] = gt0 * yn0 + (1.f - gt0) * xv0;
    out[base + j1] = gt1 * yn1 + (1.f - gt1) * xv1;
}

// ---------------- launch ----------------
extern "C" void kernel_launch(void* const* d_in, const int* in_sizes, int n_in,
                              void* d_out, int out_size)
{
    (void)in_sizes; (void)n_in; (void)out_size;
    const float* x       = (const float*)d_in[0];
    const float* W_site  = (const float*)d_in[1];
    const float* b_site  = (const float*)d_in[2];
    const float* W_bridge= (const float*)d_in[3];
    const float* b_bridge= (const float*)d_in[4];
    const float* W_out   = (const float*)d_in[5];
    const float* b_out   = (const float*)d_in[6];
    const float* gamma   = (const float*)d_in[7];
    const float* beta    = (const float*)d_in[8];
    const float* W_gate  = (const float*)d_in[9];
    const float* b_gate  = (const float*)d_in[10];
    float* out = (float*)d_out;

    static float *p_site, *p_gate, *p_y, *p_WB, *p_bB, *p_Wco, *p_bco, *p_Bmat;
    static __nv_bfloat16 *p_xh, *p_xl, *p_WsTh, *p_WsTl, *p_WgTh, *p_WgTl,
                         *p_WBTh, *p_WBTl, *p_WcoTh, *p_WcoTl, *p_mh, *p_ml;
    static cudaStream_t s1;
    static cudaEvent_t ev0, evB, evS, evG;
    static bool inited = false;
    if (!inited) {
        cudaGetSymbolAddress((void**)&p_site,  g_site);
        cudaGetSymbolAddress((void**)&p_gate,  g_gate);
        cudaGetSymbolAddress((void**)&p_y,     g_y);
        cudaGetSymbolAddress((void**)&p_WB,    g_WB);
        cudaGetSymbolAddress((void**)&p_bB,    g_bB);
        cudaGetSymbolAddress((void**)&p_Wco,   g_Wco);
        cudaGetSymbolAddress((void**)&p_bco,   g_bco);
        cudaGetSymbolAddress((void**)&p_Bmat,  g_Bmat);
        cudaGetSymbolAddress((void**)&p_xh,    g_xh);
        cudaGetSymbolAddress((void**)&p_xl,    g_xl);
        cudaGetSymbolAddress((void**)&p_WsTh,  g_WsT_h);
        cudaGetSymbolAddress((void**)&p_WsTl,  g_WsT_l);
        cudaGetSymbolAddress((void**)&p_WgTh,  g_WgT_h);
        cudaGetSymbolAddress((void**)&p_WgTl,  g_WgT_l);
        cudaGetSymbolAddress((void**)&p_WBTh,  g_WBT_h);
        cudaGetSymbolAddress((void**)&p_WBTl,  g_WBT_l);
        cudaGetSymbolAddress((void**)&p_WcoTh, g_WcoT_h);
        cudaGetSymbolAddress((void**)&p_WcoTl, g_WcoT_l);
        cudaGetSymbolAddress((void**)&p_mh,    g_mh);
        cudaGetSymbolAddress((void**)&p_ml,    g_ml);
        cudaStreamCreateWithFlags(&s1, cudaStreamNonBlocking);
        cudaEventCreateWithFlags(&ev0, cudaEventDisableTiming);
        cudaEventCreateWithFlags(&evB, cudaEventDisableTiming);
        cudaEventCreateWithFlags(&evS, cudaEventDisableTiming);
        cudaEventCreateWithFlags(&evG, cudaEventDisableTiming);
        cudaFuncSetAttribute(hgemm2_kernel, cudaFuncAttributeMaxDynamicSharedMemorySize, HG_SMEM);
        cudaFuncSetAttribute(scan_kernel, cudaFuncAttributeMaxDynamicSharedMemorySize, SCAN_SMEM);
        inited = true;
    }

    // shared prologue: x split (both branches need it)
    xcvt_kernel<<<(NT * DD) / 256, 256>>>(x);
    cudaEventRecord(ev0, 0);
    cudaStreamWaitEvent(s1, ev0, 0);

    // ---- main stream: scan-prerequisite chain gets the chip FIRST ----
    wb_kernel<<<2048, 256>>>(W_site, b_site);
    tsplit_kernel<<<dim3(32, 16), dim3(32, 8)>>>(p_WB, p_WBTh, p_WBTl, 512, 1024);
    hgemm2_kernel<<<dim3(1024/128, NT/128), 256, HG_SMEM>>>(
        p_xh, p_xl, p_WBTh, p_WBTl, p_bB, p_Bmat, NT, 1024, DD);
    cudaEventRecord(evB, 0);
    c_kernel<<<NT / 8, 256>>>(x);
    scan_kernel<<<BB, 32 * (NPROD + 1), SCAN_SMEM>>>(x);

    // ---- side stream: cheap prep concurrent; heavy GEMMs AFTER evB ----
    tsplit_kernel<<<dim3(128,16), dim3(32, 8), 0, s1>>>(W_site, p_WsTh, p_WsTl, 512, 4096);
    prep_kernel<<<256, 256, 0, s1>>>(W_bridge, b_bridge, W_out, b_out);
    tsplit_kernel<<<dim3(16, 4),  dim3(32, 8), 0, s1>>>(p_Wco,  p_WcoTh, p_WcoTl, 128, 512);
    tsplit_kernel<<<dim3(16, 16), dim3(32, 8), 0, s1>>>(W_gate, p_WgTh,  p_WgTl,  512, 512);
    cudaStreamWaitEvent(s1, evB, 0);
    hgemm2_kernel<<<dim3(CSC/128, NT/128), 256, HG_SMEM, s1>>>(
        p_xh, p_xl, p_WsTh, p_WsTl, b_site, p_site, NT, CSC, DD);
    cudaEventRecord(evS, s1);
    hgemm2_kernel<<<dim3(DD/128, NT/128), 256, HG_SMEM, s1>>>(
        p_xh, p_xl, p_WgTh, p_WgTl, b_gate, p_gate, NT, DD, DD);
    cudaEventRecord(evG, s1);

    // join: g_left (scan, main-stream order) + site (evS) -> mrec -> final GEMM
    cudaStreamWaitEvent(0, evS, 0);
    mrec_kernel<<<NT / 8, 256>>>();
    hgemm2_kernel<<<dim3(DD/128, NT/128), 256, HG_SMEM>>>(
        p_mh, p_ml, p_WcoTh, p_WcoTl, p_bco, p_y, NT, DD, 128);

    // join: gate needed for the epilogue
    cudaStreamWaitEvent(0, evG, 0);
    post_kernel<<<NT, 256>>>(x, gamma, beta, out);
}

// round 17
// speedup vs baseline: 1.5440x; 1.0635x over previous
#include <cuda_runtime.h>
#include <cuda_bf16.h>
#include <math.h>
#include <stdint.h>

// Problem dims
#define BB   4
#define LL   1024
#define DD   512
#define CHI  32
#define SS   4
#define NT   (BB*LL)          // 4096 tokens
#define CSC  (CHI*SS*CHI)     // 4096

// ---------------- scratch (__device__ globals, no allocs) ----------------
__device__ float g_site[(size_t)NT * CSC];       // x @ W_site + b_site     (64 MB)
__device__ float g_gate[(size_t)NT * DD];        // x @ W_gate + b_gate
__device__ float g_Bmat[(size_t)NT * CHI * CHI]; // B_t stored [t][r*32+l]
__device__ float g_WB[512 * 1024];               // pre-reduced site weights (fp32)
__device__ float g_bB[1024];                     // pre-reduced site bias
__device__ float g_c[(size_t)NT * CHI];          // c_t[r] = u_t @ B_t
__device__ float g_left[(size_t)NT * CHI];       // recorded left vectors
__device__ float g_y[(size_t)NT * DD];           // pre-LN y
__device__ float g_Wco[128 * 512];               // W_bridge @ W_out (fp32)
__device__ float g_bco[512];                     // b_bridge @ W_out + b_out

// pre-converted bf16 split operands
__device__ __nv_bfloat16 g_xh[(size_t)NT * DD],   g_xl[(size_t)NT * DD];
__device__ __nv_bfloat16 g_WsT_h[(size_t)CSC * DD], g_WsT_l[(size_t)CSC * DD];   // [n][k]
__device__ __nv_bfloat16 g_WgT_h[DD * DD],        g_WgT_l[DD * DD];
__device__ __nv_bfloat16 g_WBT_h[1024 * DD],      g_WBT_l[1024 * DD];
__device__ __nv_bfloat16 g_WcoT_h[DD * 128],      g_WcoT_l[DD * 128];
__device__ __nv_bfloat16 g_mh[(size_t)NT * 128],  g_ml[(size_t)NT * 128];

// ---------------- helpers ----------------
__device__ __forceinline__ uint32_t smem_u32(const void* p) {
    uint32_t a;
    asm("{ .reg .u64 t; cvta.to.shared.u64 t, %1; cvt.u32.u64 %0, t; }" : "=r"(a) : "l"(p));
    return a;
}
__device__ __forceinline__ void bsplit(float v, __nv_bfloat16& h, __nv_bfloat16& l)
{
    h = __float2bfloat16(v);
    l = __float2bfloat16(v - __bfloat162float(h));
}
__device__ __forceinline__ uint32_t pkbf2(__nv_bfloat16 a, __nv_bfloat16 b)
{
    __nv_bfloat162 t; t.x = a; t.y = b;
    uint32_t u; *(__nv_bfloat162*)&u = t; return u;
}
#define CPA16(dst, src)  asm volatile("cp.async.cg.shared.global [%0], [%1], 16;" :: "r"(dst), "l"(src))
#define CPA_COMMIT()     asm volatile("cp.async.commit_group;" ::: "memory")
#define CPA_WAIT0()      asm volatile("cp.async.wait_group 0;" ::: "memory")
#define CPA_WAIT1()      asm volatile("cp.async.wait_group 1;" ::: "memory")

#define MMA_BF16(d, a0, a1, a2, a3, b0, b1)                                   \
    asm volatile("mma.sync.aligned.m16n8k16.row.col.f32.bf16.bf16.f32 "       \
                 "{%0,%1,%2,%3}, {%4,%5,%6,%7}, {%8,%9}, {%0,%1,%2,%3};\n"    \
                 : "+f"(d[0]), "+f"(d[1]), "+f"(d[2]), "+f"(d[3])             \
                 : "r"(a0), "r"(a1), "r"(a2), "r"(a3), "r"(b0), "r"(b1))

#define LDSM4(r, addr)                                                        \
    asm volatile("ldmatrix.sync.aligned.m8n8.x4.shared.b16 {%0,%1,%2,%3}, [%4];" \
                 : "=r"((r)[0]), "=r"((r)[1]), "=r"((r)[2]), "=r"((r)[3])     \
                 : "r"(addr))

// ---------------- x -> bf16 split ----------------
__global__ void xcvt_kernel(const float* __restrict__ x)
{
    int i = blockIdx.x * 256 + threadIdx.x;      // NT*DD = 2M
    __nv_bfloat16 h, l;
    bsplit(x[i], h, l);
    g_xh[i] = h; g_xl[i] = l;
}

// ---------------- transpose + split: src[K][N] fp32 -> dh/dl[N][K] bf16 ----
__global__ void tsplit_kernel(const float* __restrict__ src,
                              __nv_bfloat16* __restrict__ dh,
                              __nv_bfloat16* __restrict__ dl, int K, int N)
{
    __shared__ float t[32][33];
    int bn = blockIdx.x * 32, bk = blockIdx.y * 32;
    int tx = threadIdx.x, ty = threadIdx.y;
#pragma unroll
    for (int i = ty; i < 32; i += 8)
        t[i][tx] = src[(size_t)(bk + i) * N + bn + tx];
    __syncthreads();
#pragma unroll
    for (int i = ty; i < 32; i += 8) {
        __nv_bfloat16 h, l;
        bsplit(t[tx][i], h, l);                  // = src[bk+tx][bn+i]
        dh[(size_t)(bn + i) * K + bk + tx] = h;
        dl[(size_t)(bn + i) * K + bk + tx] = l;
    }
}

// ---------------- prep: fuse bridge+out weights (fp32) ----------------
__global__ void prep_kernel(const float* __restrict__ Wb, const float* __restrict__ bb,
                            const float* __restrict__ Wo, const float* __restrict__ bo)
{
    int idx = blockIdx.x * blockDim.x + threadIdx.x;   // 0..65535
    int pr = idx >> 9, j = idx & 511;
    float s = 0.f;
#pragma unroll
    for (int i = 0; i < 32; ++i)
        s = fmaf(Wb[pr * 32 + i], Wo[i * 512 + j], s);
    g_Wco[idx] = s;
    if (idx < 512) {
        float c = bo[idx];
#pragma unroll
        for (int i = 0; i < 32; ++i)
            c = fmaf(bb[i], Wo[i * 512 + idx], c);
        g_bco[idx] = c;
    }
}

// ---------------- reduce W_site over physical index -> W_B (fp32) ----------
__global__ __launch_bounds__(256) void wb_kernel(const float* __restrict__ Ws,
                                                 const float* __restrict__ bs)
{
    int idx = blockIdx.x * 256 + threadIdx.x;          // 0 .. 512*1024-1
    int d = idx >> 10, rem = idx & 1023;
    int l = rem >> 5, r = rem & 31;
    const float* p = Ws + (size_t)d * 4096 + l * 128 + r;   // coalesced in r
    g_WB[(size_t)d * 1024 + r * 32 + l] = p[0] + p[32] + p[64] + p[96];
    if (idx < 1024) {
        int ll = idx >> 5, rr = idx & 31;
        const float* q = bs + ll * 128 + rr;
        g_bB[rr * 32 + ll] = q[0] + q[32] + q[64] + q[96];
    }
}

// ============ bf16-split tensor GEMM: C = A[MxK] @ B[KxN] + bias ===========
#define HG_SMEM (2 * 40960)

__device__ __forceinline__ void hg_load(uint32_t sb,
    const __nv_bfloat16* __restrict__ Ah, const __nv_bfloat16* __restrict__ Al,
    const __nv_bfloat16* __restrict__ Bh, const __nv_bfloat16* __restrict__ Bl,
    int bm, int bn, int K, int k0, int tid)
{
#pragma unroll
    for (int q = 0; q < 2; ++q) {
        int id = tid + 256 * q;                  // 0..511
        int r = id >> 2, c = id & 3;
        uint32_t so = (uint32_t)(r * 80 + c * 16);
        size_t goA = (size_t)(bm + r) * K + k0 + c * 8;
        size_t goB = (size_t)(bn + r) * K + k0 + c * 8;
        CPA16(sb + so,          Ah + goA);
        CPA16(sb + 10240 + so,  Al + goA);
        CPA16(sb + 20480 + so,  Bh + goB);
        CPA16(sb + 30720 + so,  Bl + goB);
    }
}

__device__ __forceinline__ void hg_compute(uint32_t sb, float acc[4][4][4],
                                           int m0w, int n0w, int lane)
{
    const int arow = (lane & 15);
    const int acolb = (lane >> 4) * 16;
    const int brow = (lane & 7) + ((lane >> 4) << 3);
    const int bcolb = ((lane >> 3) & 1) * 16;
#pragma unroll
    for (int kk = 0; kk < 2; ++kk) {
        const int kb = kk * 32;                  // 16 bf16 = 32 bytes
        uint32_t ah[4][4], al[4][4], bh[2][4], bl[2][4];
#pragma unroll
        for (int mi = 0; mi < 4; ++mi) {
            uint32_t adr = sb + (uint32_t)((m0w + mi * 16 + arow) * 80 + kb + acolb);
            LDSM4(ah[mi], adr);
            LDSM4(al[mi], adr + 10240);
        }
#pragma unroll
        for (int np = 0; np < 2; ++np) {
            uint32_t adr = sb + 20480 + (uint32_t)((n0w + np * 16 + brow) * 80 + kb + bcolb);
            LDSM4(bh[np], adr);
            LDSM4(bl[np], adr + 10240);
        }
#pragma unroll
        for (int ni = 0; ni < 4; ++ni) {
            uint32_t h0 = bh[ni >> 1][(ni & 1) * 2], h1 = bh[ni >> 1][(ni & 1) * 2 + 1];
            uint32_t l0 = bl[ni >> 1][(ni & 1) * 2], l1 = bl[ni >> 1][(ni & 1) * 2 + 1];
#pragma unroll
            for (int mi = 0; mi < 4; ++mi) {
                MMA_BF16(acc[mi][ni], ah[mi][0], ah[mi][1], ah[mi][2], ah[mi][3], h0, h1);
                MMA_BF16(acc[mi][ni], ah[mi][0], ah[mi][1], ah[mi][2], ah[mi][3], l0, l1);
                MMA_BF16(acc[mi][ni], al[mi][0], al[mi][1], al[mi][2], al[mi][3], h0, h1);
            }
        }
    }
}

__global__ __launch_bounds__(256, 1)
void hgemm2_kernel(const __nv_bfloat16* __restrict__ Ah, const __nv_bfloat16* __restrict__ Al,
                   const __nv_bfloat16* __restrict__ Bh, const __nv_bfloat16* __restrict__ Bl,
                   const float* __restrict__ bias, float* __restrict__ C,
                   int M, int N, int K)
{
    extern __shared__ __align__(16) char smem[];
    const int tid = threadIdx.x;
    const int warp = tid >> 5, lane = tid & 31;
    const int g = lane >> 2, tg = lane & 3;
    const int m0w = (warp >> 2) * 64;            // 0 | 64
    const int n0w = (warp & 3) * 32;             // 0..96
    const int bm = blockIdx.y * 128, bn = blockIdx.x * 128;
    const uint32_t sb = smem_u32(smem);

    float acc[4][4][4];
#pragma unroll
    for (int i = 0; i < 4; ++i)
#pragma unroll
        for (int j = 0; j < 4; ++j)
#pragma unroll
            for (int e = 0; e < 4; ++e) acc[i][j][e] = 0.f;

    const int nk = K >> 5;
    hg_load(sb, Ah, Al, Bh, Bl, bm, bn, K, 0, tid);
    CPA_COMMIT();
    for (int i = 0; i < nk; ++i) {
        if (i + 1 < nk) {
            hg_load(sb + ((i + 1) & 1) * 40960, Ah, Al, Bh, Bl, bm, bn, K, (i + 1) * 32, tid);
            CPA_COMMIT();
            CPA_WAIT1();
        } else {
            CPA_WAIT0();
        }
        __syncthreads();
        hg_compute(sb + (uint32_t)((i & 1) * 40960), acc, m0w, n0w, lane);
        __syncthreads();
    }

#pragma unroll
    for (int mi = 0; mi < 4; ++mi) {
        int row = bm + m0w + mi * 16 + g;
#pragma unroll
        for (int ni = 0; ni < 4; ++ni) {
            int col = bn + n0w + ni * 8 + 2 * tg;
            float b0 = bias[col], b1 = bias[col + 1];
            *(float2*)&C[(size_t)row * N + col] =
                make_float2(acc[mi][ni][0] + b0, acc[mi][ni][1] + b1);
            *(float2*)&C[(size_t)(row + 8) * N + col] =
                make_float2(acc[mi][ni][2] + b0, acc[mi][ni][3] + b1);
        }
    }
}

// ---------------- c_t[r] = sum_l u_t[l] * B_t[l][r] (8 tokens/block) -------
__global__ __launch_bounds__(256) void c_kernel(const float* __restrict__ x)
{
    int t = blockIdx.x * 8 + (threadIdx.x >> 5);
    int r = threadIdx.x & 31;
    float u = x[(size_t)t * DD + r];           // lane l holds u_l
    const float* brow = g_Bmat + (size_t)t * 1024 + r * 32;
    float4 b4[8];
#pragma unroll
    for (int q = 0; q < 8; ++q) b4[q] = __ldg((const float4*)(brow + 4 * q));
    float c = 0.f;
#pragma unroll
    for (int q = 0; q < 8; ++q) {
        c = fmaf(__shfl_sync(0xffffffffu, u, 4 * q + 0), b4[q].x, c);
        c = fmaf(__shfl_sync(0xffffffffu, u, 4 * q + 1), b4[q].y, c);
        c = fmaf(__shfl_sync(0xffffffffu, u, 4 * q + 2), b4[q].z, c);
        c = fmaf(__shfl_sync(0xffffffffu, u, 4 * q + 3), b4[q].w, c);
    }
    g_c[(size_t)t * 32 + r] = c;
}

// ========== sequential scan: producer/consumer smem ring ==========
// Block = 384 threads (12 warps): wids 3,7 exit after init; consumer = wid 11
// (alone on its SMSP); 9 producers (depth-2 cp.async pipelining).
// Consumer broadcast via smem vbuf (1 STS + 8 broadcast LDS.128) instead of
// 32 SHFLs -> MIO issue per step roughly halved.
#define NS    32
#define STGB  4864                      // 32*144 + 128 (c) + 128 (u)
#define SCAN_SMEM (NS * STGB)
#define NPROD 9
#define SCAN_THREADS 384

__device__ __forceinline__ void prod_issue(uint32_t base, size_t tg0, int s,
                                           int lane, const float* __restrict__ x)
{
    const char* gB = (const char*)(g_Bmat + (tg0 + s) * 1024);
#pragma unroll
    for (int q = 0; q < 8; ++q) {
        int i = lane + 32 * q;                       // 0..255 float4 chunks
        CPA16(base + (uint32_t)((i >> 3) * 144 + (i & 7) * 16), gB + i * 16);
    }
    if (lane < 8) {
        CPA16(base + 4608u + lane * 16,
              (const char*)(g_c + (tg0 + s) * 32) + lane * 16);
    } else if (lane < 16) {
        CPA16(base + 4736u + (lane - 8) * 16,
              (const char*)(x + (tg0 + s) * DD) + (lane - 8) * 16);
    }
}

__global__ __launch_bounds__(SCAN_THREADS, 1) void scan_kernel(const float* __restrict__ x)
{
    extern __shared__ __align__(16) char ring[];
    __shared__ volatile int flags[NS];
    __shared__ volatile int progress;
    __shared__ __align__(16) float vbuf[2][32];

    const int b = blockIdx.x, tid = threadIdx.x;
    const int wid = tid >> 5, lane = tid & 31;
    const size_t tg0 = (size_t)b * LL;

    for (int i = tid; i < NS; i += SCAN_THREADS) flags[i] = 0;
    if (tid == 0) progress = 0;
    __syncthreads();

    if (wid == 3 || wid == 7) return;   // keep the consumer's SMSP clear

    if (wid != 11) {
        // ---- producers: p in 0..8, steps s ≡ p (mod 9), depth-2 pipeline ----
        const int p = wid - (wid > 3 ? 1 : 0) - (wid > 7 ? 1 : 0);
        uint32_t rbase = smem_u32(ring);
        int s = p;
        prod_issue(rbase + (uint32_t)(s % NS) * STGB, tg0, s, lane, x);
        CPA_COMMIT();
        for (int next = s + NPROD; next < LL; next += NPROD) {
            if (next >= NS) {
                while (progress < next - NS + 1) { __nanosleep(64); }
            }
            prod_issue(rbase + (uint32_t)(next % NS) * STGB, tg0, next, lane, x);
            CPA_COMMIT();
            CPA_WAIT1();                      // oldest group (step s) done
            __threadfence_block();
            __syncwarp();
            if (lane == 0) flags[s % NS] = s + 1;
            s = next;
        }
        CPA_WAIT0();
        __threadfence_block();
        __syncwarp();
        if (lane == 0) flags[s % NS] = s + 1;
    } else {
        // ---- consumer: the serial recurrence, smem-transpose broadcast ----
        float v = 0.f;
        float* lp = g_left + tg0 * 32 + lane;
        int slot = 0;
        while (flags[0] < 1) {}
#pragma unroll 1
        for (int t = 0; t < LL; ++t) {
            const char* stg = ring + (size_t)slot * STGB;
            // B column for this lane (independent of v -> issue first)
            const float4* br = (const float4*)(stg + lane * 144);
            float4 B[8];
#pragma unroll
            for (int q = 0; q < 8; ++q) B[q] = br[q];
            float cc = *(const float*)(stg + 4608 + 4 * lane);
            float uu = *(const float*)(stg + 4736 + 4 * lane);
            int nslot = slot + 1; if (nslot == NS) nslot = 0;
            int nf = flags[nslot];            // early probe; hides under compute

            // broadcast v via smem (double-buffered; one syncwarp per step)
            float* vb = vbuf[t & 1];
            vb[lane] = v;
            __syncwarp();
            const float4* vv4 = (const float4*)vb;
            float4 vv[8];
#pragma unroll
            for (int q = 0; q < 8; ++q) vv[q] = vv4[q];   // broadcast LDS.128

            float w[8], s[8];
#pragma unroll
            for (int q = 0; q < 8; ++q) {
                float wq, sq;
                wq = vv[q].x * B[q].x;            sq = vv[q].x * vv[q].x;
                wq = fmaf(vv[q].y, B[q].y, wq);   sq = fmaf(vv[q].y, vv[q].y, sq);
                wq = fmaf(vv[q].z, B[q].z, wq);   sq = fmaf(vv[q].z, vv[q].z, sq);
                wq = fmaf(vv[q].w, B[q].w, wq);   sq = fmaf(vv[q].w, vv[q].w, sq);
                w[q] = wq; s[q] = sq;
            }
            float wt = ((w[0] + w[1]) + (w[2] + w[3])) + ((w[4] + w[5]) + (w[6] + w[7]));
            float st = ((s[0] + s[1]) + (s[2] + s[3])) + ((s[4] + s[5]) + (s[6] + s[7]));
            float alpha = rsqrtf(st + 1e-24f);    // st==0 -> alpha*v == 0 == h0
            *lp = fmaf(alpha, v, uu);
            v = fmaf(alpha, wt, cc);

            lp += 32;
            if (lane == 0) progress = t + 1;
            if (t + 1 < LL && nf < t + 2) {
                while (flags[nslot] < t + 2) {}
            }
            slot = nslot;
        }
    }
}

// ------- recover Mt per token; emit bf16 split for the final GEMM ----------
// Warp-per-token, float4 streaming loads; 8 tokens per 256-thread block.
__global__ __launch_bounds__(256) void mrec_kernel()
{
    int t = blockIdx.x * 8 + (threadIdx.x >> 5);
    int lane = threadIdx.x & 31;
    float lf = g_left[(size_t)t * 32 + lane];       // lane l holds left[l]
    const float* row = g_site + (size_t)t * CSC;

    float4 m = make_float4(0.f, 0.f, 0.f, 0.f);
#pragma unroll
    for (int l = 0; l < 32; ++l) {
        float s = __shfl_sync(0xffffffffu, lf, l);
        float4 rv = __ldcs((const float4*)(row + l * 128 + 4 * lane));
        m.x = fmaf(s, rv.x, m.x);
        m.y = fmaf(s, rv.y, m.y);
        m.z = fmaf(s, rv.z, m.z);
        m.w = fmaf(s, rv.w, m.w);
    }
    __nv_bfloat16 hx, lx, hy, ly, hz, lz, hw, lw;
    bsplit(m.x, hx, lx); bsplit(m.y, hy, ly);
    bsplit(m.z, hz, lz); bsplit(m.w, hw, lw);
    size_t o = (size_t)t * 128 + 4 * lane;
    uint2 ph = make_uint2(pkbf2(hx, hy), pkbf2(hz, hw));
    uint2 pl = make_uint2(pkbf2(lx, ly), pkbf2(lz, lw));
    *(uint2*)(g_mh + o) = ph;
    *(uint2*)(g_ml + o) = pl;
}

// ---------------- LayerNorm + sigmoid-gated residual ----------------
__global__ __launch_bounds__(256) void post_kernel(const float* __restrict__ x,
                                                   const float* __restrict__ gamma,
                                                   const float* __restrict__ beta,
                                                   float* __restrict__ out)
{
    __shared__ float red[256];
    int t = blockIdx.x, tid = threadIdx.x;
    size_t base = (size_t)t * DD;
    int j0 = tid, j1 = tid + 256;
    float y0 = g_y[base + j0], y1 = g_y[base + j1];

    red[tid] = y0 + y1;
    __syncthreads();
    for (int st = 128; st > 0; st >>= 1) {
        if (tid < st) red[tid] += red[tid + st];
        __syncthreads();
    }
    float mu = red[0] * (1.f / 512.f);
    __syncthreads();

    float d0 = y0 - mu, d1 = y1 - mu;
    red[tid] = d0 * d0 + d1 * d1;
    __syncthreads();
    for (int st = 128; st > 0; st >>= 1) {
        if (tid < st) red[tid] += red[tid + st];
        __syncthreads();
    }
    float var = red[0] * (1.f / 512.f);
    float rstd = rsqrtf(var + 1e-6f);

    float yn0 = d0 * rstd * gamma[j0] + beta[j0];
    float yn1 = d1 * rstd * gamma[j1] + beta[j1];
    float gl0 = g_gate[base + j0], gl1 = g_gate[base + j1];
    float gt0 = 1.f / (1.f + expf(-gl0));
    float gt1 = 1.f / (1.f + expf(-gl1));
    float xv0 = x[base + j0], xv1 = x[base + j1];
    out[base + j0] = gt0 * yn0 + (1.f - gt0) * xv0;
    out[base + j1] = gt1 * yn1 + (1.f - gt1) * xv1;
}

// ---------------- launch ----------------
extern "C" void kernel_launch(void* const* d_in, const int* in_sizes, int n_in,
                              void* d_out, int out_size)
{
    (void)in_sizes; (void)n_in; (void)out_size;
    const float* x       = (const float*)d_in[0];
    const float* W_site  = (const float*)d_in[1];
    const float* b_site  = (const float*)d_in[2];
    const float* W_bridge= (const float*)d_in[3];
    const float* b_bridge= (const float*)d_in[4];
    const float* W_out   = (const float*)d_in[5];
    const float* b_out   = (const float*)d_in[6];
    const float* gamma   = (const float*)d_in[7];
    const float* beta    = (const float*)d_in[8];
    const float* W_gate  = (const float*)d_in[9];
    const float* b_gate  = (const float*)d_in[10];
    float* out = (float*)d_out;

    static float *p_site, *p_gate, *p_y, *p_WB, *p_bB, *p_Wco, *p_bco, *p_Bmat;
    static __nv_bfloat16 *p_xh, *p_xl, *p_WsTh, *p_WsTl, *p_WgTh, *p_WgTl,
                         *p_WBTh, *p_WBTl, *p_WcoTh, *p_WcoTl, *p_mh, *p_ml;
    static cudaStream_t s1;
    static cudaEvent_t ev0, evW, evB, evS, evG;
    static bool inited = false;
    if (!inited) {
        cudaGetSymbolAddress((void**)&p_site,  g_site);
        cudaGetSymbolAddress((void**)&p_gate,  g_gate);
        cudaGetSymbolAddress((void**)&p_y,     g_y);
        cudaGetSymbolAddress((void**)&p_WB,    g_WB);
        cudaGetSymbolAddress((void**)&p_bB,    g_bB);
        cudaGetSymbolAddress((void**)&p_Wco,   g_Wco);
        cudaGetSymbolAddress((void**)&p_bco,   g_bco);
        cudaGetSymbolAddress((void**)&p_Bmat,  g_Bmat);
        cudaGetSymbolAddress((void**)&p_xh,    g_xh);
        cudaGetSymbolAddress((void**)&p_xl,    g_xl);
        cudaGetSymbolAddress((void**)&p_WsTh,  g_WsT_h);
        cudaGetSymbolAddress((void**)&p_WsTl,  g_WsT_l);
        cudaGetSymbolAddress((void**)&p_WgTh,  g_WgT_h);
        cudaGetSymbolAddress((void**)&p_WgTl,  g_WgT_l);
        cudaGetSymbolAddress((void**)&p_WBTh,  g_WBT_h);
        cudaGetSymbolAddress((void**)&p_WBTl,  g_WBT_l);
        cudaGetSymbolAddress((void**)&p_WcoTh, g_WcoT_h);
        cudaGetSymbolAddress((void**)&p_WcoTl, g_WcoT_l);
        cudaGetSymbolAddress((void**)&p_mh,    g_mh);
        cudaGetSymbolAddress((void**)&p_ml,    g_ml);
        cudaStreamCreateWithFlags(&s1, cudaStreamNonBlocking);
        cudaEventCreateWithFlags(&ev0, cudaEventDisableTiming);
        cudaEventCreateWithFlags(&evW, cudaEventDisableTiming);
        cudaEventCreateWithFlags(&evB, cudaEventDisableTiming);
        cudaEventCreateWithFlags(&evS, cudaEventDisableTiming);
        cudaEventCreateWithFlags(&evG, cudaEventDisableTiming);
        cudaFuncSetAttribute(hgemm2_kernel, cudaFuncAttributeMaxDynamicSharedMemorySize, HG_SMEM);
        cudaFuncSetAttribute(scan_kernel, cudaFuncAttributeMaxDynamicSharedMemorySize, SCAN_SMEM);
        inited = true;
    }

    // fork: side stream starts W_B prep concurrently with xcvt
    cudaEventRecord(ev0, 0);
    cudaStreamWaitEvent(s1, ev0, 0);
    wb_kernel<<<2048, 256, 0, s1>>>(W_site, b_site);
    tsplit_kernel<<<dim3(32, 16), dim3(32, 8), 0, s1>>>(p_WB, p_WBTh, p_WBTl, 512, 1024);
    cudaEventRecord(evW, s1);

    // ---- main stream: xcvt -> (join W_B) -> B-hgemm -> c -> scan ----
    xcvt_kernel<<<(NT * DD) / 256, 256>>>(x);
    cudaStreamWaitEvent(0, evW, 0);
    hgemm2_kernel<<<dim3(1024/128, NT/128), 256, HG_SMEM>>>(
        p_xh, p_xl, p_WBTh, p_WBTl, p_bB, p_Bmat, NT, 1024, DD);
    cudaEventRecord(evB, 0);
    c_kernel<<<NT / 8, 256>>>(x);
    scan_kernel<<<BB, SCAN_THREADS, SCAN_SMEM>>>(x);

    // ---- side stream: remaining prep; heavy GEMMs AFTER evB ----
    tsplit_kernel<<<dim3(128,16), dim3(32, 8), 0, s1>>>(W_site, p_WsTh, p_WsTl, 512, 4096);
    prep_kernel<<<256, 256, 0, s1>>>(W_bridge, b_bridge, W_out, b_out);
    tsplit_kernel<<<dim3(16, 4),  dim3(32, 8), 0, s1>>>(p_Wco,  p_WcoTh, p_WcoTl, 128, 512);
    tsplit_kernel<<<dim3(16, 16), dim3(32, 8), 0, s1>>>(W_gate, p_WgTh,  p_WgTl,  512, 512);
    cudaStreamWaitEvent(s1, evB, 0);
    hgemm2_kernel<<<dim3(CSC/128, NT/128), 256, HG_SMEM, s1>>>(
        p_xh, p_xl, p_WsTh, p_WsTl, b_site, p_site, NT, CSC, DD);
    cudaEventRecord(evS, s1);
    hgemm2_kernel<<<dim3(DD/128, NT/128), 256, HG_SMEM, s1>>>(
        p_xh, p_xl, p_WgTh, p_WgTl, b_gate, p_gate, NT, DD, DD);
    cudaEventRecord(evG, s1);

    // join: g_left (scan, main-stream order) + site (evS) -> mrec -> final GEMM
    cudaStreamWaitEvent(0, evS, 0);
    mrec_kernel<<<NT / 8, 256>>>();
    hgemm2_kernel<<<dim3(DD/128, NT/128), 256, HG_SMEM>>>(
        p_mh, p_ml, p_WcoTh, p_WcoTl, p_bco, p_y, NT, DD, 128);

    // join: gate needed for the epilogue
    cudaStreamWaitEvent(0, evG, 0);
    post_kernel<<<NT, 256>>>(x, gamma, beta, out);
}